// round 1
// baseline (speedup 1.0000x reference)
#include <cuda_runtime.h>
#include <math.h>

#define NN   204800      // total nodes
#define DD   64          // embed dim
#define EE   3276800     // edges
#define NB   8192        // graphs
#define HID  1600        // 25 * 64

// ---------------- scratch (device globals; no allocation) ----------------
__device__ int   g_deg[NN];
__device__ float g_dinv[NN];
__device__ float g_h [(size_t)NN * DD];   // x @ W_conv
__device__ float g_h2[(size_t)NN * DD];   // aggregated -> relu'd H
__device__ float g_o1[(size_t)NB * HID];  // relu(H @ W1 + b1)

// ---------------- degree ----------------
__global__ void k_deg_init() {
    int i = blockIdx.x * blockDim.x + threadIdx.x;
    if (i < NN) g_deg[i] = 1;               // self loop
}

__global__ void k_deg_count(const int* __restrict__ dst) {
    int e = blockIdx.x * blockDim.x + threadIdx.x;
    if (e < EE) atomicAdd(&g_deg[dst[e]], 1);
}

__global__ void k_dinv() {
    int i = blockIdx.x * blockDim.x + threadIdx.x;
    if (i < NN) g_dinv[i] = rsqrtf((float)g_deg[i]);
}

// ---------------- generic fp32 GEMM: C = op(A@B + bias) ----------------
// BM=128, BN=64, BK=16; 256 threads; 8x4 per-thread tile.
// Requires M%128==0, N%64==0, K%16==0 (holds for both call sites).
__global__ __launch_bounds__(256)
void k_gemm(const float* __restrict__ A, const float* __restrict__ B,
            float* __restrict__ C, const float* __restrict__ bias,
            int M, int N, int K, int doRelu) {
    __shared__ float As[16][128];
    __shared__ float Bs[16][64];

    const int tid = threadIdx.x;
    const int bm = blockIdx.y * 128;
    const int bn = blockIdx.x * 64;
    const int tx = tid & 15;       // 16 cols of threads (TN=4)
    const int ty = tid >> 4;       // 16 rows of threads (TM=8)

    float acc[8][4];
#pragma unroll
    for (int i = 0; i < 8; i++)
#pragma unroll
        for (int j = 0; j < 4; j++) acc[i][j] = 0.f;

    const float* Ab = A + (size_t)bm * K;
    const float* Bb = B + bn;

    for (int k0 = 0; k0 < K; k0 += 16) {
        // load A tile (128x16) as 512 float4, 2 per thread, store transposed
#pragma unroll
        for (int t = 0; t < 2; t++) {
            int v   = tid + t * 256;
            int row = v >> 2;            // 0..127
            int kc  = (v & 3) * 4;       // 0,4,8,12
            float4 a = *(const float4*)(Ab + (size_t)row * K + k0 + kc);
            As[kc + 0][row] = a.x;
            As[kc + 1][row] = a.y;
            As[kc + 2][row] = a.z;
            As[kc + 3][row] = a.w;
        }
        // load B tile (16x64) as 256 float4, 1 per thread
        {
            int krow = tid >> 4;         // 0..15
            int col  = (tid & 15) * 4;   // 0..60
            float4 b = *(const float4*)(Bb + (size_t)(k0 + krow) * N + col);
            *(float4*)&Bs[krow][col] = b;
        }
        __syncthreads();

#pragma unroll
        for (int k = 0; k < 16; k++) {
            float a[8], b[4];
            *(float4*)(a + 0) = *(const float4*)&As[k][ty * 8 + 0];
            *(float4*)(a + 4) = *(const float4*)&As[k][ty * 8 + 4];
            *(float4*)(b + 0) = *(const float4*)&Bs[k][tx * 4];
#pragma unroll
            for (int i = 0; i < 8; i++)
#pragma unroll
                for (int j = 0; j < 4; j++)
                    acc[i][j] = fmaf(a[i], b[j], acc[i][j]);
        }
        __syncthreads();
    }

    float bv[4];
#pragma unroll
    for (int j = 0; j < 4; j++)
        bv[j] = bias ? bias[bn + tx * 4 + j] : 0.f;

#pragma unroll
    for (int i = 0; i < 8; i++) {
        int r = bm + ty * 8 + i;
        float4 o;
        float v0 = acc[i][0] + bv[0];
        float v1 = acc[i][1] + bv[1];
        float v2 = acc[i][2] + bv[2];
        float v3 = acc[i][3] + bv[3];
        if (doRelu) {
            v0 = fmaxf(v0, 0.f); v1 = fmaxf(v1, 0.f);
            v2 = fmaxf(v2, 0.f); v3 = fmaxf(v3, 0.f);
        }
        o.x = v0; o.y = v1; o.z = v2; o.w = v3;
        *(float4*)(C + (size_t)r * N + bn + tx * 4) = o;
    }
}

// ---------------- self-loop init: h2 = h * dinv^2 ----------------
__global__ void k_selfloop() {
    size_t i = (size_t)blockIdx.x * blockDim.x + threadIdx.x;
    if (i < (size_t)NN * DD) {
        float di = g_dinv[i >> 6];
        g_h2[i] = g_h[i] * di * di;
    }
}

// ---------------- edge scatter: one warp per edge ----------------
__global__ void k_scatter(const int* __restrict__ src, const int* __restrict__ dst) {
    int gt   = blockIdx.x * blockDim.x + threadIdx.x;
    int e    = gt >> 5;
    int lane = gt & 31;
    if (e >= EE) return;
    int s = src[e];
    int d = dst[e];
    float norm = g_dinv[s] * g_dinv[d];
    float2 v = *(const float2*)&g_h[(size_t)s * DD + lane * 2];
    float* o = &g_h2[(size_t)d * DD + lane * 2];
    atomicAdd(o + 0, v.x * norm);
    atomicAdd(o + 1, v.y * norm);
}

// ---------------- bias + relu in place ----------------
__global__ void k_bias_relu(const float* __restrict__ bc) {
    size_t i = (size_t)blockIdx.x * blockDim.x + threadIdx.x;
    if (i < (size_t)NN * DD)
        g_h2[i] = fmaxf(g_h2[i] + bc[i & 63], 0.f);
}

// ---------------- head: logits = o1 @ W2 + b2, softmax ----------------
__global__ void k_head(const float* __restrict__ W2, const float* __restrict__ b2,
                       float* __restrict__ out) {
    int warp = (blockIdx.x * blockDim.x + threadIdx.x) >> 5;
    int lane = threadIdx.x & 31;
    if (warp >= NB) return;
    const float* row = &g_o1[(size_t)warp * HID];
    float s0 = 0.f, s1 = 0.f;
    for (int j = lane; j < HID; j += 32) {
        float v = row[j];
        s0 = fmaf(v, W2[j * 2 + 0], s0);
        s1 = fmaf(v, W2[j * 2 + 1], s1);
    }
#pragma unroll
    for (int off = 16; off > 0; off >>= 1) {
        s0 += __shfl_down_sync(0xffffffffu, s0, off);
        s1 += __shfl_down_sync(0xffffffffu, s1, off);
    }
    if (lane == 0) {
        float l0 = s0 + b2[0];
        float l1 = s1 + b2[1];
        float m  = fmaxf(l0, l1);
        float e0 = expf(l0 - m);
        float e1 = expf(l1 - m);
        float inv = 1.f / (e0 + e1);
        out[warp * 2 + 0] = e0 * inv;
        out[warp * 2 + 1] = e1 * inv;
    }
}

// ---------------- launch ----------------
extern "C" void kernel_launch(void* const* d_in, const int* in_sizes, int n_in,
                              void* d_out, int out_size) {
    const float* x  = (const float*)d_in[0];
    const int*   ei = (const int*)  d_in[1];
    // d_in[2] = batch (implicit: contiguous blocks of 25 nodes) — unused
    const float* Wc = (const float*)d_in[3];
    const float* bc = (const float*)d_in[4];
    const float* W1 = (const float*)d_in[5];
    const float* b1 = (const float*)d_in[6];
    const float* W2 = (const float*)d_in[7];
    const float* b2 = (const float*)d_in[8];
    float* out = (float*)d_out;

    float *ph, *ph2, *po1;
    cudaGetSymbolAddress((void**)&ph,  g_h);
    cudaGetSymbolAddress((void**)&ph2, g_h2);
    cudaGetSymbolAddress((void**)&po1, g_o1);

    const int* src = ei;        // edge_index[0]
    const int* dst = ei + EE;   // edge_index[1]

    // degrees
    k_deg_init <<<(NN + 255) / 256, 256>>>();
    k_deg_count<<<(EE + 255) / 256, 256>>>(dst);
    k_dinv     <<<(NN + 255) / 256, 256>>>();

    // h = x @ W_conv   (M=204800, N=64, K=64)
    {
        dim3 grid(DD / 64, NN / 128);
        k_gemm<<<grid, 256>>>(x, Wc, ph, nullptr, NN, DD, DD, 0);
    }

    // h2 = self-loop contribution, then scatter edges, then bias+relu
    k_selfloop <<<((size_t)NN * DD + 255) / 256, 256>>>();
    k_scatter  <<<((size_t)EE * 32 + 255) / 256, 256>>>(src, dst);
    k_bias_relu<<<((size_t)NN * DD + 255) / 256, 256>>>(bc);

    // o1 = relu(H @ W1 + b1)   (M=8192, N=1600, K=1600)
    {
        dim3 grid(HID / 64, NB / 128);
        k_gemm<<<grid, 256>>>(ph2, W1, po1, b1, NB, HID, HID, 1);
    }

    // logits + softmax
    k_head<<<(NB * 32 + 255) / 256, 256>>>(W2, b2, out);
}

// round 3
// speedup vs baseline: 1.7110x; 1.7110x over previous
#include <cuda_runtime.h>
#include <math.h>
#include <stdint.h>

#define NN   204800      // total nodes
#define DD   64          // embed dim
#define EE   3276800     // edges
#define NB   8192        // graphs
#define HID  1600        // 25 * 64

// mma.sync GEMM tiling
#define BM 128
#define BN 64
#define BK 32
#define KITERS (HID / BK)   // 50

// smem float strides (bank-conflict-free, 16B aligned)
#define ASTRIDE 44          // 128 rows x (32 + pad 12)
#define BSTRIDE 72          // 32 rows  x (64 + pad 8)
#define A_BUF_F (BM * ASTRIDE)          // 5632 floats
#define B_BUF_F (BK * BSTRIDE)          // 2304 floats
#define SM_B_BASE (2 * A_BUF_F)         // 11264
#define SM_TOTAL_B ((2 * A_BUF_F + 2 * B_BUF_F) * 4)   // 63488 bytes

// ---------------- scratch (device globals; no allocation) ----------------
__device__ int   g_deg[NN];
__device__ float g_dinv[NN];
__device__ float g_h [(size_t)NN * DD];    // x @ W_conv
__device__ float g_h2[(size_t)NN * DD];    // aggregated -> relu'd H
__device__ float g_o1[(size_t)NB * HID];   // relu(H @ W1 + b1)

// ---------------- degree ----------------
__global__ void k_deg_init() {
    int i = blockIdx.x * blockDim.x + threadIdx.x;
    if (i < NN) g_deg[i] = 1;               // self loop
}
__global__ void k_deg_count(const int* __restrict__ dst) {
    int e = blockIdx.x * blockDim.x + threadIdx.x;
    if (e < EE) atomicAdd(&g_deg[dst[e]], 1);
}
__global__ void k_dinv() {
    int i = blockIdx.x * blockDim.x + threadIdx.x;
    if (i < NN) g_dinv[i] = rsqrtf((float)g_deg[i]);
}

// ---------------- FFMA GEMM (conv: M=204800, N=64, K=64) ----------------
__global__ __launch_bounds__(256)
void k_gemm(const float* __restrict__ A, const float* __restrict__ B,
            float* __restrict__ C, const float* __restrict__ bias,
            int M, int N, int K, int doRelu) {
    __shared__ float As[16][128];
    __shared__ float Bs[16][64];
    const int tid = threadIdx.x;
    const int bm = blockIdx.y * 128;
    const int bn = blockIdx.x * 64;
    const int tx = tid & 15;
    const int ty = tid >> 4;

    float acc[8][4];
#pragma unroll
    for (int i = 0; i < 8; i++)
#pragma unroll
        for (int j = 0; j < 4; j++) acc[i][j] = 0.f;

    const float* Ab = A + (size_t)bm * K;
    const float* Bb = B + bn;

    for (int k0 = 0; k0 < K; k0 += 16) {
#pragma unroll
        for (int t = 0; t < 2; t++) {
            int v   = tid + t * 256;
            int row = v >> 2;
            int kc  = (v & 3) * 4;
            float4 a = *(const float4*)(Ab + (size_t)row * K + k0 + kc);
            As[kc + 0][row] = a.x;
            As[kc + 1][row] = a.y;
            As[kc + 2][row] = a.z;
            As[kc + 3][row] = a.w;
        }
        {
            int krow = tid >> 4;
            int col  = (tid & 15) * 4;
            float4 b = *(const float4*)(Bb + (size_t)(k0 + krow) * N + col);
            *(float4*)&Bs[krow][col] = b;
        }
        __syncthreads();
#pragma unroll
        for (int k = 0; k < 16; k++) {
            float a[8], b[4];
            *(float4*)(a + 0) = *(const float4*)&As[k][ty * 8 + 0];
            *(float4*)(a + 4) = *(const float4*)&As[k][ty * 8 + 4];
            *(float4*)(b + 0) = *(const float4*)&Bs[k][tx * 4];
#pragma unroll
            for (int i = 0; i < 8; i++)
#pragma unroll
                for (int j = 0; j < 4; j++)
                    acc[i][j] = fmaf(a[i], b[j], acc[i][j]);
        }
        __syncthreads();
    }

    float bv[4];
#pragma unroll
    for (int j = 0; j < 4; j++)
        bv[j] = bias ? bias[bn + tx * 4 + j] : 0.f;
#pragma unroll
    for (int i = 0; i < 8; i++) {
        int r = bm + ty * 8 + i;
        float v0 = acc[i][0] + bv[0];
        float v1 = acc[i][1] + bv[1];
        float v2 = acc[i][2] + bv[2];
        float v3 = acc[i][3] + bv[3];
        if (doRelu) {
            v0 = fmaxf(v0, 0.f); v1 = fmaxf(v1, 0.f);
            v2 = fmaxf(v2, 0.f); v3 = fmaxf(v3, 0.f);
        }
        float4 o; o.x = v0; o.y = v1; o.z = v2; o.w = v3;
        *(float4*)(C + (size_t)r * N + bn + tx * 4) = o;
    }
}

// ================= tf32 mma.sync GEMM =================
__device__ __forceinline__ uint32_t f2tf(float f) {
    uint32_t u;
    asm("cvt.rna.tf32.f32 %0, %1;" : "=r"(u) : "f"(f));
    return u;
}
__device__ __forceinline__ void mma_tf32(float* c, const uint32_t* a, const uint32_t* b) {
    asm volatile(
        "mma.sync.aligned.m16n8k8.row.col.f32.tf32.tf32.f32 "
        "{%0,%1,%2,%3}, {%4,%5,%6,%7}, {%8,%9}, {%0,%1,%2,%3};"
        : "+f"(c[0]), "+f"(c[1]), "+f"(c[2]), "+f"(c[3])
        : "r"(a[0]), "r"(a[1]), "r"(a[2]), "r"(a[3]), "r"(b[0]), "r"(b[1]));
}

// C = relu(A @ B + bias). A: [M=8192, K=1600], B: [K=1600, N=1600] (W1, no transpose).
// grid = (HID/BN, NB/BM), 256 threads = 8 warps, warp tile 32x32.
__global__ __launch_bounds__(256, 2)
void k_gemm_mma(const float* __restrict__ A, const float* __restrict__ B,
                float* __restrict__ C, const float* __restrict__ bias) {
    extern __shared__ float sm[];
#define AS_(b, r, c) sm[(b) * A_BUF_F + (r) * ASTRIDE + (c)]
#define BS_(b, k, n) sm[SM_B_BASE + (b) * B_BUF_F + (k) * BSTRIDE + (n)]

    const int tid = threadIdx.x;
    const int wid = tid >> 5;
    const int lid = tid & 31;
    const int g   = lid >> 2;    // groupID (0..7)
    const int tq  = lid & 3;     // threadID_in_group (0..3)
    const int wm  = wid >> 1;    // 0..3  (rows, 32 each)
    const int wn  = wid & 1;     // 0..1  (cols, 32 each)
    const int bm  = blockIdx.y * BM;
    const int bn  = blockIdx.x * BN;

    const float* Ag = A + (size_t)bm * HID;      // A[bm..][.]
    const float* Bg = B + bn;                    // B[.][bn..]

    float acc[2][4][4];
#pragma unroll
    for (int mt = 0; mt < 2; mt++)
#pragma unroll
        for (int nt = 0; nt < 4; nt++)
#pragma unroll
            for (int j = 0; j < 4; j++) acc[mt][nt][j] = 0.f;

    // per-thread load coordinates
    const int a_row = tid >> 3;            // 0..31 (then +32,+64,+96)
    const int a_c4  = (tid & 7) * 4;       // col in floats
    const int b_row = tid >> 4;            // 0..15 (then +16)
    const int b_c4  = (tid & 15) * 4;

    float4 pa[4], pb[2];

    // prologue: load tile 0 into regs, store to smem buf 0
#pragma unroll
    for (int i = 0; i < 4; i++)
        pa[i] = *(const float4*)(Ag + (size_t)(a_row + i * 32) * HID + a_c4);
#pragma unroll
    for (int i = 0; i < 2; i++)
        pb[i] = *(const float4*)(Bg + (size_t)(b_row + i * 16) * HID + b_c4);
#pragma unroll
    for (int i = 0; i < 4; i++) {
        uint4 t = make_uint4(f2tf(pa[i].x), f2tf(pa[i].y), f2tf(pa[i].z), f2tf(pa[i].w));
        *(uint4*)&AS_(0, a_row + i * 32, a_c4) = t;
    }
#pragma unroll
    for (int i = 0; i < 2; i++) {
        uint4 t = make_uint4(f2tf(pb[i].x), f2tf(pb[i].y), f2tf(pb[i].z), f2tf(pb[i].w));
        *(uint4*)&BS_(0, b_row + i * 16, b_c4) = t;
    }
    __syncthreads();

    for (int k0 = 0; k0 < KITERS; k0++) {
        const int b = k0 & 1;
        if (k0 + 1 < KITERS) {
            const float* An = Ag + (k0 + 1) * BK;
            const float* Bn = Bg + (size_t)(k0 + 1) * BK * HID;
#pragma unroll
            for (int i = 0; i < 4; i++)
                pa[i] = *(const float4*)(An + (size_t)(a_row + i * 32) * HID + a_c4);
#pragma unroll
            for (int i = 0; i < 2; i++)
                pb[i] = *(const float4*)(Bn + (size_t)(b_row + i * 16) * HID + b_c4);
        }

        // compute on buffer b
#pragma unroll
        for (int ks = 0; ks < 4; ks++) {
            const int kb = ks * 8;
            uint32_t af[2][4], bf[4][2];
#pragma unroll
            for (int mt = 0; mt < 2; mt++) {
                const int r = wm * 32 + mt * 16 + g;
                af[mt][0] = __float_as_uint(AS_(b, r,     kb + tq));
                af[mt][1] = __float_as_uint(AS_(b, r + 8, kb + tq));
                af[mt][2] = __float_as_uint(AS_(b, r,     kb + tq + 4));
                af[mt][3] = __float_as_uint(AS_(b, r + 8, kb + tq + 4));
            }
#pragma unroll
            for (int nt = 0; nt < 4; nt++) {
                const int n = wn * 32 + nt * 8 + g;
                bf[nt][0] = __float_as_uint(BS_(b, kb + tq,     n));
                bf[nt][1] = __float_as_uint(BS_(b, kb + tq + 4, n));
            }
#pragma unroll
            for (int mt = 0; mt < 2; mt++)
#pragma unroll
                for (int nt = 0; nt < 4; nt++)
                    mma_tf32(acc[mt][nt], af[mt], bf[nt]);
        }

        if (k0 + 1 < KITERS) {
            const int nb = b ^ 1;
#pragma unroll
            for (int i = 0; i < 4; i++) {
                uint4 t = make_uint4(f2tf(pa[i].x), f2tf(pa[i].y), f2tf(pa[i].z), f2tf(pa[i].w));
                *(uint4*)&AS_(nb, a_row + i * 32, a_c4) = t;
            }
#pragma unroll
            for (int i = 0; i < 2; i++) {
                uint4 t = make_uint4(f2tf(pb[i].x), f2tf(pb[i].y), f2tf(pb[i].z), f2tf(pb[i].w));
                *(uint4*)&BS_(nb, b_row + i * 16, b_c4) = t;
            }
        }
        __syncthreads();
    }

    // epilogue: bias + relu, write C
#pragma unroll
    for (int mt = 0; mt < 2; mt++) {
        const int r0 = bm + wm * 32 + mt * 16 + g;
#pragma unroll
        for (int nt = 0; nt < 4; nt++) {
            const int cb = bn + wn * 32 + nt * 8 + tq * 2;
            const float b0 = bias[cb], b1 = bias[cb + 1];
            float2 o;
            o.x = fmaxf(acc[mt][nt][0] + b0, 0.f);
            o.y = fmaxf(acc[mt][nt][1] + b1, 0.f);
            *(float2*)(C + (size_t)r0 * HID + cb) = o;
            o.x = fmaxf(acc[mt][nt][2] + b0, 0.f);
            o.y = fmaxf(acc[mt][nt][3] + b1, 0.f);
            *(float2*)(C + (size_t)(r0 + 8) * HID + cb) = o;
        }
    }
#undef AS_
#undef BS_
}

// ---------------- self-loop init: h2 = h * dinv^2 ----------------
__global__ void k_selfloop() {
    size_t i = (size_t)blockIdx.x * blockDim.x + threadIdx.x;
    if (i < (size_t)NN * DD) {
        float di = g_dinv[i >> 6];
        g_h2[i] = g_h[i] * di * di;
    }
}

// ---------------- edge scatter: one warp per edge ----------------
__global__ void k_scatter(const int* __restrict__ src, const int* __restrict__ dst) {
    int gt   = blockIdx.x * blockDim.x + threadIdx.x;
    int e    = gt >> 5;
    int lane = gt & 31;
    if (e >= EE) return;
    int s = src[e];
    int d = dst[e];
    float norm = g_dinv[s] * g_dinv[d];
    float2 v = *(const float2*)&g_h[(size_t)s * DD + lane * 2];
    float* o = &g_h2[(size_t)d * DD + lane * 2];
    atomicAdd(o + 0, v.x * norm);
    atomicAdd(o + 1, v.y * norm);
}

// ---------------- bias + relu in place ----------------
__global__ void k_bias_relu(const float* __restrict__ bc) {
    size_t i = (size_t)blockIdx.x * blockDim.x + threadIdx.x;
    if (i < (size_t)NN * DD)
        g_h2[i] = fmaxf(g_h2[i] + bc[i & 63], 0.f);
}

// ---------------- head: logits = o1 @ W2 + b2, softmax ----------------
__global__ void k_head(const float* __restrict__ W2, const float* __restrict__ b2,
                       float* __restrict__ out) {
    int warp = (blockIdx.x * blockDim.x + threadIdx.x) >> 5;
    int lane = threadIdx.x & 31;
    if (warp >= NB) return;
    const float* row = &g_o1[(size_t)warp * HID];
    float s0 = 0.f, s1 = 0.f;
    for (int j = lane; j < HID; j += 32) {
        float v = row[j];
        s0 = fmaf(v, W2[j * 2 + 0], s0);
        s1 = fmaf(v, W2[j * 2 + 1], s1);
    }
#pragma unroll
    for (int off = 16; off > 0; off >>= 1) {
        s0 += __shfl_down_sync(0xffffffffu, s0, off);
        s1 += __shfl_down_sync(0xffffffffu, s1, off);
    }
    if (lane == 0) {
        float l0 = s0 + b2[0];
        float l1 = s1 + b2[1];
        float m  = fmaxf(l0, l1);
        float e0 = expf(l0 - m);
        float e1 = expf(l1 - m);
        float inv = 1.f / (e0 + e1);
        out[warp * 2 + 0] = e0 * inv;
        out[warp * 2 + 1] = e1 * inv;
    }
}

// ---------------- launch ----------------
extern "C" void kernel_launch(void* const* d_in, const int* in_sizes, int n_in,
                              void* d_out, int out_size) {
    const float* x  = (const float*)d_in[0];
    const int*   ei = (const int*)  d_in[1];
    const float* Wc = (const float*)d_in[3];
    const float* bc = (const float*)d_in[4];
    const float* W1 = (const float*)d_in[5];
    const float* b1 = (const float*)d_in[6];
    const float* W2 = (const float*)d_in[7];
    const float* b2 = (const float*)d_in[8];
    float* out = (float*)d_out;

    float *ph, *ph2, *po1;
    cudaGetSymbolAddress((void**)&ph,  g_h);
    cudaGetSymbolAddress((void**)&ph2, g_h2);
    cudaGetSymbolAddress((void**)&po1, g_o1);

    static int smem_set = 0;
    if (!smem_set) {
        cudaFuncSetAttribute(k_gemm_mma, cudaFuncAttributeMaxDynamicSharedMemorySize,
                             SM_TOTAL_B);
        smem_set = 1;
    }

    const int* src = ei;        // edge_index[0]
    const int* dst = ei + EE;   // edge_index[1]

    // degrees
    k_deg_init <<<(NN + 255) / 256, 256>>>();
    k_deg_count<<<(EE + 255) / 256, 256>>>(dst);
    k_dinv     <<<(NN + 255) / 256, 256>>>();

    // h = x @ W_conv   (M=204800, N=64, K=64)  — FFMA path
    {
        dim3 grid(DD / 64, NN / 128);
        k_gemm<<<grid, 256>>>(x, Wc, ph, nullptr, NN, DD, DD, 0);
    }

    // h2 = self-loop contribution, then scatter edges, then bias+relu
    k_selfloop <<<((size_t)NN * DD + 255) / 256, 256>>>();
    k_scatter  <<<((size_t)EE * 32 + 255) / 256, 256>>>(src, dst);
    k_bias_relu<<<((size_t)NN * DD + 255) / 256, 256>>>(bc);

    // o1 = relu(H @ W1 + b1)   (M=8192, N=1600, K=1600)  — tf32 mma.sync
    {
        dim3 grid(HID / BN, NB / BM);
        k_gemm_mma<<<grid, 256, SM_TOTAL_B>>>(ph2, W1, po1, b1);
    }

    // logits + softmax
    k_head<<<(NB * 32 + 255) / 256, 256>>>(W2, b2, out);
}

// round 4
// speedup vs baseline: 2.1700x; 1.2683x over previous
#include <cuda_runtime.h>
#include <math.h>
#include <stdint.h>

#define NN   204800      // total nodes
#define DD   64          // embed dim
#define EE   3276800     // edges
#define NB   8192        // graphs
#define HID  1600        // 25 * 64

// mma.sync GEMM tiling
#define BM 128
#define BN 64
#define BK 32

// smem float strides (bank-conflict-free, 16B aligned)
#define ASTRIDE 44          // 128 rows x (32 + pad 12)
#define BSTRIDE 72          // 32 rows  x (64 + pad 8)
#define A_BUF_F (BM * ASTRIDE)          // 5632 floats
#define B_BUF_F (BK * BSTRIDE)          // 2304 floats
#define SM_B_BASE (2 * A_BUF_F)         // 11264
#define SM_TOTAL_B ((2 * A_BUF_F + 2 * B_BUF_F) * 4)   // 63488 bytes

// ---------------- scratch (device globals; no allocation) ----------------
__device__ int   g_deg[NN];
__device__ float g_dinv[NN];
__device__ float g_h [(size_t)NN * DD];    // x @ W_conv
__device__ float g_h2[(size_t)NN * DD];    // aggregated -> relu'd H
__device__ float g_o1[(size_t)NB * HID];   // relu(H @ W1 + b1)

// ---------------- degree ----------------
__global__ void k_deg_init() {
    int i = blockIdx.x * blockDim.x + threadIdx.x;
    if (i < NN) g_deg[i] = 1;               // self loop
}
__global__ void k_deg_count(const int* __restrict__ dst) {
    int e = blockIdx.x * blockDim.x + threadIdx.x;
    if (e < EE) atomicAdd(&g_deg[dst[e]], 1);
}
__global__ void k_dinv() {
    int i = blockIdx.x * blockDim.x + threadIdx.x;
    if (i < NN) g_dinv[i] = rsqrtf((float)g_deg[i]);
}

// ================= tf32 mma.sync GEMM =================
__device__ __forceinline__ uint32_t f2tf(float f) {
    uint32_t u;
    asm("cvt.rna.tf32.f32 %0, %1;" : "=r"(u) : "f"(f));
    return u;
}
__device__ __forceinline__ void mma_tf32(float* c, const uint32_t* a, const uint32_t* b) {
    asm volatile(
        "mma.sync.aligned.m16n8k8.row.col.f32.tf32.tf32.f32 "
        "{%0,%1,%2,%3}, {%4,%5,%6,%7}, {%8,%9}, {%0,%1,%2,%3};"
        : "+f"(c[0]), "+f"(c[1]), "+f"(c[2]), "+f"(c[3])
        : "r"(a[0]), "r"(a[1]), "r"(a[2]), "r"(a[3]), "r"(b[0]), "r"(b[1]));
}

// C[M, NTOT] = op(A[M, KTOT] @ B[KTOT, NTOT] (+ bias))
// grid = (NTOT/BN, M/BM), 256 threads = 8 warps, warp tile 32x32, KIT = KTOT/BK.
template<int KTOT, int NTOT, int KIT, bool RELU, bool BIAS>
__global__ __launch_bounds__(256, 2)
void k_gemm_mma(const float* __restrict__ A, const float* __restrict__ B,
                float* __restrict__ C, const float* __restrict__ bias) {
    extern __shared__ float sm[];
#define AS_(b, r, c) sm[(b) * A_BUF_F + (r) * ASTRIDE + (c)]
#define BS_(b, k, n) sm[SM_B_BASE + (b) * B_BUF_F + (k) * BSTRIDE + (n)]

    const int tid = threadIdx.x;
    const int wid = tid >> 5;
    const int lid = tid & 31;
    const int g   = lid >> 2;    // groupID (0..7)
    const int tq  = lid & 3;     // threadID_in_group (0..3)
    const int wm  = wid >> 1;    // 0..3  (rows, 32 each)
    const int wn  = wid & 1;     // 0..1  (cols, 32 each)
    const int bm  = blockIdx.y * BM;
    const int bn  = blockIdx.x * BN;

    const float* Ag = A + (size_t)bm * KTOT;
    const float* Bg = B + bn;

    float acc[2][4][4];
#pragma unroll
    for (int mt = 0; mt < 2; mt++)
#pragma unroll
        for (int nt = 0; nt < 4; nt++)
#pragma unroll
            for (int j = 0; j < 4; j++) acc[mt][nt][j] = 0.f;

    const int a_row = tid >> 3;            // 0..31 (then +32,+64,+96)
    const int a_c4  = (tid & 7) * 4;
    const int b_row = tid >> 4;            // 0..15 (then +16)
    const int b_c4  = (tid & 15) * 4;

    float4 pa[4], pb[2];

    // prologue: tile 0 -> buf 0
#pragma unroll
    for (int i = 0; i < 4; i++)
        pa[i] = *(const float4*)(Ag + (size_t)(a_row + i * 32) * KTOT + a_c4);
#pragma unroll
    for (int i = 0; i < 2; i++)
        pb[i] = *(const float4*)(Bg + (size_t)(b_row + i * 16) * NTOT + b_c4);
#pragma unroll
    for (int i = 0; i < 4; i++) {
        uint4 t = make_uint4(f2tf(pa[i].x), f2tf(pa[i].y), f2tf(pa[i].z), f2tf(pa[i].w));
        *(uint4*)&AS_(0, a_row + i * 32, a_c4) = t;
    }
#pragma unroll
    for (int i = 0; i < 2; i++) {
        uint4 t = make_uint4(f2tf(pb[i].x), f2tf(pb[i].y), f2tf(pb[i].z), f2tf(pb[i].w));
        *(uint4*)&BS_(0, b_row + i * 16, b_c4) = t;
    }
    __syncthreads();

    for (int k0 = 0; k0 < KIT; k0++) {
        const int b = k0 & 1;
        if (k0 + 1 < KIT) {
            const float* An = Ag + (k0 + 1) * BK;
            const float* Bn = Bg + (size_t)(k0 + 1) * BK * NTOT;
#pragma unroll
            for (int i = 0; i < 4; i++)
                pa[i] = *(const float4*)(An + (size_t)(a_row + i * 32) * KTOT + a_c4);
#pragma unroll
            for (int i = 0; i < 2; i++)
                pb[i] = *(const float4*)(Bn + (size_t)(b_row + i * 16) * NTOT + b_c4);
        }

#pragma unroll
        for (int ks = 0; ks < 4; ks++) {
            const int kb = ks * 8;
            uint32_t af[2][4], bf[4][2];
#pragma unroll
            for (int mt = 0; mt < 2; mt++) {
                const int r = wm * 32 + mt * 16 + g;
                af[mt][0] = __float_as_uint(AS_(b, r,     kb + tq));
                af[mt][1] = __float_as_uint(AS_(b, r + 8, kb + tq));
                af[mt][2] = __float_as_uint(AS_(b, r,     kb + tq + 4));
                af[mt][3] = __float_as_uint(AS_(b, r + 8, kb + tq + 4));
            }
#pragma unroll
            for (int nt = 0; nt < 4; nt++) {
                const int n = wn * 32 + nt * 8 + g;
                bf[nt][0] = __float_as_uint(BS_(b, kb + tq,     n));
                bf[nt][1] = __float_as_uint(BS_(b, kb + tq + 4, n));
            }
#pragma unroll
            for (int mt = 0; mt < 2; mt++)
#pragma unroll
                for (int nt = 0; nt < 4; nt++)
                    mma_tf32(acc[mt][nt], af[mt], bf[nt]);
        }

        if (k0 + 1 < KIT) {
            const int nb = b ^ 1;
#pragma unroll
            for (int i = 0; i < 4; i++) {
                uint4 t = make_uint4(f2tf(pa[i].x), f2tf(pa[i].y), f2tf(pa[i].z), f2tf(pa[i].w));
                *(uint4*)&AS_(nb, a_row + i * 32, a_c4) = t;
            }
#pragma unroll
            for (int i = 0; i < 2; i++) {
                uint4 t = make_uint4(f2tf(pb[i].x), f2tf(pb[i].y), f2tf(pb[i].z), f2tf(pb[i].w));
                *(uint4*)&BS_(nb, b_row + i * 16, b_c4) = t;
            }
        }
        __syncthreads();
    }

    // epilogue
#pragma unroll
    for (int mt = 0; mt < 2; mt++) {
        const int r0 = bm + wm * 32 + mt * 16 + g;
#pragma unroll
        for (int nt = 0; nt < 4; nt++) {
            const int cb = bn + wn * 32 + nt * 8 + tq * 2;
            float b0 = 0.f, b1 = 0.f;
            if (BIAS) { b0 = bias[cb]; b1 = bias[cb + 1]; }
            float2 o;
            o.x = acc[mt][nt][0] + b0;
            o.y = acc[mt][nt][1] + b1;
            if (RELU) { o.x = fmaxf(o.x, 0.f); o.y = fmaxf(o.y, 0.f); }
            *(float2*)(C + (size_t)r0 * NTOT + cb) = o;
            o.x = acc[mt][nt][2] + b0;
            o.y = acc[mt][nt][3] + b1;
            if (RELU) { o.x = fmaxf(o.x, 0.f); o.y = fmaxf(o.y, 0.f); }
            *(float2*)(C + (size_t)(r0 + 8) * NTOT + cb) = o;
        }
    }
#undef AS_
#undef BS_
}

// ---------------- self-loop init: h2 = h * dinv^2 ----------------
__global__ void k_selfloop() {
    size_t i = (size_t)blockIdx.x * blockDim.x + threadIdx.x;
    if (i < (size_t)NN * DD) {
        float di = g_dinv[i >> 6];
        g_h2[i] = g_h[i] * di * di;
    }
}

// ---------------- edge scatter: half-warp per edge, vector red ----------------
__global__ void k_scatter(const int* __restrict__ src, const int* __restrict__ dst) {
    int gt = blockIdx.x * blockDim.x + threadIdx.x;
    int e  = gt >> 4;
    int l  = gt & 15;
    if (e >= EE) return;
    int s = src[e];
    int d = dst[e];
    float norm = g_dinv[s] * g_dinv[d];
    float4 v = *(const float4*)&g_h[(size_t)s * DD + l * 4];
    float* o = &g_h2[(size_t)d * DD + l * 4];
    asm volatile("red.global.add.v4.f32 [%0], {%1, %2, %3, %4};"
                 :: "l"(o), "f"(v.x * norm), "f"(v.y * norm),
                    "f"(v.z * norm), "f"(v.w * norm)
                 : "memory");
}

// ---------------- bias + relu in place ----------------
__global__ void k_bias_relu(const float* __restrict__ bc) {
    size_t i = (size_t)blockIdx.x * blockDim.x + threadIdx.x;
    if (i < (size_t)NN * DD)
        g_h2[i] = fmaxf(g_h2[i] + bc[i & 63], 0.f);
}

// ---------------- head: logits = o1 @ W2 + b2, softmax ----------------
__global__ void k_head(const float* __restrict__ W2, const float* __restrict__ b2,
                       float* __restrict__ out) {
    int warp = (blockIdx.x * blockDim.x + threadIdx.x) >> 5;
    int lane = threadIdx.x & 31;
    if (warp >= NB) return;
    const float* row = &g_o1[(size_t)warp * HID];
    float s0 = 0.f, s1 = 0.f;
    for (int j = lane; j < HID; j += 32) {
        float v = row[j];
        s0 = fmaf(v, W2[j * 2 + 0], s0);
        s1 = fmaf(v, W2[j * 2 + 1], s1);
    }
#pragma unroll
    for (int off = 16; off > 0; off >>= 1) {
        s0 += __shfl_down_sync(0xffffffffu, s0, off);
        s1 += __shfl_down_sync(0xffffffffu, s1, off);
    }
    if (lane == 0) {
        float l0 = s0 + b2[0];
        float l1 = s1 + b2[1];
        float m  = fmaxf(l0, l1);
        float e0 = expf(l0 - m);
        float e1 = expf(l1 - m);
        float inv = 1.f / (e0 + e1);
        out[warp * 2 + 0] = e0 * inv;
        out[warp * 2 + 1] = e1 * inv;
    }
}

// ---------------- launch ----------------
extern "C" void kernel_launch(void* const* d_in, const int* in_sizes, int n_in,
                              void* d_out, int out_size) {
    const float* x  = (const float*)d_in[0];
    const int*   ei = (const int*)  d_in[1];
    const float* Wc = (const float*)d_in[3];
    const float* bc = (const float*)d_in[4];
    const float* W1 = (const float*)d_in[5];
    const float* b1 = (const float*)d_in[6];
    const float* W2 = (const float*)d_in[7];
    const float* b2 = (const float*)d_in[8];
    float* out = (float*)d_out;

    float *ph, *ph2, *po1;
    cudaGetSymbolAddress((void**)&ph,  g_h);
    cudaGetSymbolAddress((void**)&ph2, g_h2);
    cudaGetSymbolAddress((void**)&po1, g_o1);

    static int smem_set = 0;
    if (!smem_set) {
        cudaFuncSetAttribute(k_gemm_mma<HID, HID, HID / BK, true, true>,
                             cudaFuncAttributeMaxDynamicSharedMemorySize, SM_TOTAL_B);
        cudaFuncSetAttribute(k_gemm_mma<DD, DD, DD / BK, false, false>,
                             cudaFuncAttributeMaxDynamicSharedMemorySize, SM_TOTAL_B);
        smem_set = 1;
    }

    const int* src = ei;        // edge_index[0]
    const int* dst = ei + EE;   // edge_index[1]

    // degrees
    k_deg_init <<<(NN + 255) / 256, 256>>>();
    k_deg_count<<<(EE + 255) / 256, 256>>>(dst);
    k_dinv     <<<(NN + 255) / 256, 256>>>();

    // h = x @ W_conv   (M=204800, N=64, K=64)  — tf32 mma
    {
        dim3 grid(DD / BN, NN / BM);
        k_gemm_mma<DD, DD, DD / BK, false, false>
            <<<grid, 256, SM_TOTAL_B>>>(x, Wc, ph, nullptr);
    }

    // h2 = self-loop contribution, then scatter edges, then bias+relu
    k_selfloop <<<((size_t)NN * DD + 255) / 256, 256>>>();
    k_scatter  <<<((size_t)EE * 16 + 255) / 256, 256>>>(src, dst);
    k_bias_relu<<<((size_t)NN * DD + 255) / 256, 256>>>(bc);

    // o1 = relu(H @ W1 + b1)   (M=8192, N=1600, K=1600)  — tf32 mma
    {
        dim3 grid(HID / BN, NB / BM);
        k_gemm_mma<HID, HID, HID / BK, true, true>
            <<<grid, 256, SM_TOTAL_B>>>(ph2, W1, po1, b1);
    }

    // logits + softmax
    k_head<<<(NB * 32 + 255) / 256, 256>>>(W2, b2, out);
}

// round 5
// speedup vs baseline: 2.8652x; 1.3204x over previous
#include <cuda_runtime.h>
#include <cuda_bf16.h>
#include <math.h>
#include <stdint.h>

#define NN   204800      // total nodes
#define DD   64          // embed dim
#define EE   3276800     // edges
#define NB   8192        // graphs
#define HID  1600        // 25 * 64

// GEMM tiling (both kernels)
#define BM 128
#define BN 64
#define BK 32

// ---- tf32 kernel smem (dynamic) ----
#define ASTRIDE 44
#define BSTRIDE 72
#define A_BUF_F (BM * ASTRIDE)
#define B_BUF_F (BK * BSTRIDE)
#define SM_B_BASE (2 * A_BUF_F)
#define SM_TOTAL_B ((2 * A_BUF_F + 2 * B_BUF_F) * 4)

// ---- bf16 kernel smem (static, uint32 words) ----
#define ASTR2 20            // 16 data words + 4 pad
#define BSTR2 72            // 64 data words + 8 pad

// ---------------- scratch (device globals; no allocation) ----------------
__device__ int   g_deg[NN];
__device__ float g_dinv[NN];
__device__ float g_h  [(size_t)NN * DD];      // x @ W_conv
__device__ float g_h2 [(size_t)NN * DD];      // fp32 aggregation buffer
__device__ __nv_bfloat16 g_h2b[(size_t)NN * DD];   // relu(h2+bc) in bf16
__device__ __nv_bfloat16 g_W1b[(size_t)HID * HID]; // W1 in bf16
__device__ float g_o1[(size_t)NB * HID];      // relu(H @ W1 + b1)

// ---------------- degree ----------------
__global__ void k_deg_init() {
    int i = blockIdx.x * blockDim.x + threadIdx.x;
    if (i < NN) g_deg[i] = 1;
}
__global__ void k_deg_count(const int* __restrict__ dst) {
    int e = blockIdx.x * blockDim.x + threadIdx.x;
    if (e < EE) atomicAdd(&g_deg[dst[e]], 1);
}
__global__ void k_dinv() {
    int i = blockIdx.x * blockDim.x + threadIdx.x;
    if (i < NN) g_dinv[i] = rsqrtf((float)g_deg[i]);
}

// ---------------- W1 -> bf16 ----------------
__global__ void k_cvt_w1(const float* __restrict__ W1) {
    size_t i4 = ((size_t)blockIdx.x * blockDim.x + threadIdx.x) * 4;
    if (i4 >= (size_t)HID * HID) return;
    float4 v = *(const float4*)(W1 + i4);
    uint2 o;
    o.x = ((uint32_t)__bfloat16_as_ushort(__float2bfloat16(v.x)))
        | ((uint32_t)__bfloat16_as_ushort(__float2bfloat16(v.y)) << 16);
    o.y = ((uint32_t)__bfloat16_as_ushort(__float2bfloat16(v.z)))
        | ((uint32_t)__bfloat16_as_ushort(__float2bfloat16(v.w)) << 16);
    *(uint2*)(g_W1b + i4) = o;
}

// ================= tf32 mma.sync GEMM (conv) =================
__device__ __forceinline__ uint32_t f2tf(float f) {
    uint32_t u;
    asm("cvt.rna.tf32.f32 %0, %1;" : "=r"(u) : "f"(f));
    return u;
}
__device__ __forceinline__ void mma_tf32(float* c, const uint32_t* a, const uint32_t* b) {
    asm volatile(
        "mma.sync.aligned.m16n8k8.row.col.f32.tf32.tf32.f32 "
        "{%0,%1,%2,%3}, {%4,%5,%6,%7}, {%8,%9}, {%0,%1,%2,%3};"
        : "+f"(c[0]), "+f"(c[1]), "+f"(c[2]), "+f"(c[3])
        : "r"(a[0]), "r"(a[1]), "r"(a[2]), "r"(a[3]), "r"(b[0]), "r"(b[1]));
}

// C = A @ B ; optionally also C2[r][c] = C[r][c] * dinv[r]^2 (fused self-loop)
template<int KTOT, int NTOT, int KIT>
__global__ __launch_bounds__(256, 2)
void k_gemm_conv(const float* __restrict__ A, const float* __restrict__ B,
                 float* __restrict__ C, float* __restrict__ C2,
                 const float* __restrict__ dinv) {
    extern __shared__ float sm[];
#define AS_(b, r, c) sm[(b) * A_BUF_F + (r) * ASTRIDE + (c)]
#define BS_(b, k, n) sm[SM_B_BASE + (b) * B_BUF_F + (k) * BSTRIDE + (n)]

    const int tid = threadIdx.x;
    const int wid = tid >> 5;
    const int lid = tid & 31;
    const int g   = lid >> 2;
    const int tq  = lid & 3;
    const int wm  = wid >> 1;
    const int wn  = wid & 1;
    const int bm  = blockIdx.y * BM;
    const int bn  = blockIdx.x * BN;

    const float* Ag = A + (size_t)bm * KTOT;
    const float* Bg = B + bn;

    float acc[2][4][4];
#pragma unroll
    for (int mt = 0; mt < 2; mt++)
#pragma unroll
        for (int nt = 0; nt < 4; nt++)
#pragma unroll
            for (int j = 0; j < 4; j++) acc[mt][nt][j] = 0.f;

    const int a_row = tid >> 3;
    const int a_c4  = (tid & 7) * 4;
    const int b_row = tid >> 4;
    const int b_c4  = (tid & 15) * 4;

    float4 pa[4], pb[2];
#pragma unroll
    for (int i = 0; i < 4; i++)
        pa[i] = *(const float4*)(Ag + (size_t)(a_row + i * 32) * KTOT + a_c4);
#pragma unroll
    for (int i = 0; i < 2; i++)
        pb[i] = *(const float4*)(Bg + (size_t)(b_row + i * 16) * NTOT + b_c4);
#pragma unroll
    for (int i = 0; i < 4; i++) {
        uint4 t = make_uint4(f2tf(pa[i].x), f2tf(pa[i].y), f2tf(pa[i].z), f2tf(pa[i].w));
        *(uint4*)&AS_(0, a_row + i * 32, a_c4) = t;
    }
#pragma unroll
    for (int i = 0; i < 2; i++) {
        uint4 t = make_uint4(f2tf(pb[i].x), f2tf(pb[i].y), f2tf(pb[i].z), f2tf(pb[i].w));
        *(uint4*)&BS_(0, b_row + i * 16, b_c4) = t;
    }
    __syncthreads();

    for (int k0 = 0; k0 < KIT; k0++) {
        const int b = k0 & 1;
        if (k0 + 1 < KIT) {
            const float* An = Ag + (k0 + 1) * BK;
            const float* Bn = Bg + (size_t)(k0 + 1) * BK * NTOT;
#pragma unroll
            for (int i = 0; i < 4; i++)
                pa[i] = *(const float4*)(An + (size_t)(a_row + i * 32) * KTOT + a_c4);
#pragma unroll
            for (int i = 0; i < 2; i++)
                pb[i] = *(const float4*)(Bn + (size_t)(b_row + i * 16) * NTOT + b_c4);
        }
#pragma unroll
        for (int ks = 0; ks < 4; ks++) {
            const int kb = ks * 8;
            uint32_t af[2][4], bf[4][2];
#pragma unroll
            for (int mt = 0; mt < 2; mt++) {
                const int r = wm * 32 + mt * 16 + g;
                af[mt][0] = __float_as_uint(AS_(b, r,     kb + tq));
                af[mt][1] = __float_as_uint(AS_(b, r + 8, kb + tq));
                af[mt][2] = __float_as_uint(AS_(b, r,     kb + tq + 4));
                af[mt][3] = __float_as_uint(AS_(b, r + 8, kb + tq + 4));
            }
#pragma unroll
            for (int nt = 0; nt < 4; nt++) {
                const int n = wn * 32 + nt * 8 + g;
                bf[nt][0] = __float_as_uint(BS_(b, kb + tq,     n));
                bf[nt][1] = __float_as_uint(BS_(b, kb + tq + 4, n));
            }
#pragma unroll
            for (int mt = 0; mt < 2; mt++)
#pragma unroll
                for (int nt = 0; nt < 4; nt++)
                    mma_tf32(acc[mt][nt], af[mt], bf[nt]);
        }
        if (k0 + 1 < KIT) {
            const int nb = b ^ 1;
#pragma unroll
            for (int i = 0; i < 4; i++) {
                uint4 t = make_uint4(f2tf(pa[i].x), f2tf(pa[i].y), f2tf(pa[i].z), f2tf(pa[i].w));
                *(uint4*)&AS_(nb, a_row + i * 32, a_c4) = t;
            }
#pragma unroll
            for (int i = 0; i < 2; i++) {
                uint4 t = make_uint4(f2tf(pb[i].x), f2tf(pb[i].y), f2tf(pb[i].z), f2tf(pb[i].w));
                *(uint4*)&BS_(nb, b_row + i * 16, b_c4) = t;
            }
        }
        __syncthreads();
    }

#pragma unroll
    for (int mt = 0; mt < 2; mt++) {
        const int r0 = bm + wm * 32 + mt * 16 + g;
        const float d0 = dinv[r0],     dd0 = d0 * d0;
        const float d1 = dinv[r0 + 8], dd1 = d1 * d1;
#pragma unroll
        for (int nt = 0; nt < 4; nt++) {
            const int cb = bn + wn * 32 + nt * 8 + tq * 2;
            float2 o;
            o.x = acc[mt][nt][0]; o.y = acc[mt][nt][1];
            *(float2*)(C + (size_t)r0 * NTOT + cb) = o;
            float2 s; s.x = o.x * dd0; s.y = o.y * dd0;
            *(float2*)(C2 + (size_t)r0 * NTOT + cb) = s;
            o.x = acc[mt][nt][2]; o.y = acc[mt][nt][3];
            *(float2*)(C + (size_t)(r0 + 8) * NTOT + cb) = o;
            s.x = o.x * dd1; s.y = o.y * dd1;
            *(float2*)(C2 + (size_t)(r0 + 8) * NTOT + cb) = s;
        }
    }
#undef AS_
#undef BS_
}

// ================= bf16 mma.sync GEMM (dense head) =================
__device__ __forceinline__ void mma_bf16(float* c, const uint32_t* a, const uint32_t* b) {
    asm volatile(
        "mma.sync.aligned.m16n8k16.row.col.f32.bf16.bf16.f32 "
        "{%0,%1,%2,%3}, {%4,%5,%6,%7}, {%8,%9}, {%0,%1,%2,%3};"
        : "+f"(c[0]), "+f"(c[1]), "+f"(c[2]), "+f"(c[3])
        : "r"(a[0]), "r"(a[1]), "r"(a[2]), "r"(a[3]), "r"(b[0]), "r"(b[1]));
}

// C[NB, HID] = relu(A[NB, HID]bf16 @ B[HID, HID]bf16 + bias)
// grid = (HID/BN, NB/BM), 256 threads = 8 warps, warp tile 32x32.
#define KIT2 (HID / BK)     // 50
__global__ __launch_bounds__(256, 2)
void k_gemm_bf16(const __nv_bfloat16* __restrict__ A, const __nv_bfloat16* __restrict__ B,
                 float* __restrict__ C, const float* __restrict__ bias) {
    // A tile: [128 rows][16 words (32 bf16)] pad->20 ; B tile k-pair packed: [16 k2][64 n] pad->72
    __shared__ uint32_t smA[2][BM][ASTR2];
    __shared__ uint32_t smB[2][BK / 2][BSTR2];

    const int tid = threadIdx.x;
    const int wid = tid >> 5;
    const int lid = tid & 31;
    const int g   = lid >> 2;
    const int tq  = lid & 3;
    const int wm  = wid >> 1;
    const int wn  = wid & 1;
    const int bm  = blockIdx.y * BM;
    const int bn  = blockIdx.x * BN;

    const __nv_bfloat16* Ag = A + (size_t)bm * HID;
    const __nv_bfloat16* Bg = B + bn;

    float acc[2][4][4];
#pragma unroll
    for (int mt = 0; mt < 2; mt++)
#pragma unroll
        for (int nt = 0; nt < 4; nt++)
#pragma unroll
            for (int j = 0; j < 4; j++) acc[mt][nt][j] = 0.f;

    // A: 128 rows x 64B = 512 uint4 -> 2 per thread
    const int a_row = tid >> 2;            // 0..63 (then +64)
    const int a_c4  = tid & 3;             // uint4 index in row
    // B: thread owns k2 = tid>>4 (0..15), 4 n-values at n4*4
    const int b_k2  = tid >> 4;
    const int b_n4  = (tid & 15) * 4;      // n offset (bf16 elems)

    uint4 pa[2];
    uint2 pb0, pb1;

    // prologue
#pragma unroll
    for (int i = 0; i < 2; i++)
        pa[i] = *(const uint4*)(Ag + (size_t)(a_row + i * 64) * HID + a_c4 * 8);
    pb0 = *(const uint2*)(Bg + (size_t)(2 * b_k2)     * HID + b_n4);
    pb1 = *(const uint2*)(Bg + (size_t)(2 * b_k2 + 1) * HID + b_n4);
#pragma unroll
    for (int i = 0; i < 2; i++)
        *(uint4*)&smA[0][a_row + i * 64][a_c4 * 4] = pa[i];
    {
        uint4 w;
        w.x = __byte_perm(pb0.x, pb1.x, 0x5410);
        w.y = __byte_perm(pb0.x, pb1.x, 0x7632);
        w.z = __byte_perm(pb0.y, pb1.y, 0x5410);
        w.w = __byte_perm(pb0.y, pb1.y, 0x7632);
        *(uint4*)&smB[0][b_k2][b_n4] = w;
    }
    __syncthreads();

    for (int k0 = 0; k0 < KIT2; k0++) {
        const int b = k0 & 1;
        if (k0 + 1 < KIT2) {
            const __nv_bfloat16* An = Ag + (k0 + 1) * BK;
            const __nv_bfloat16* Bn = Bg + (size_t)(k0 + 1) * BK * HID;
#pragma unroll
            for (int i = 0; i < 2; i++)
                pa[i] = *(const uint4*)(An + (size_t)(a_row + i * 64) * HID + a_c4 * 8);
            pb0 = *(const uint2*)(Bn + (size_t)(2 * b_k2)     * HID + b_n4);
            pb1 = *(const uint2*)(Bn + (size_t)(2 * b_k2 + 1) * HID + b_n4);
        }

#pragma unroll
        for (int ks = 0; ks < 2; ks++) {
            const int kw = ks * 8;       // word offset (16 bf16 per ks)
            uint32_t af[2][4], bf[4][2];
#pragma unroll
            for (int mt = 0; mt < 2; mt++) {
                const int r = wm * 32 + mt * 16 + g;
                af[mt][0] = smA[b][r    ][kw + tq];
                af[mt][1] = smA[b][r + 8][kw + tq];
                af[mt][2] = smA[b][r    ][kw + tq + 4];
                af[mt][3] = smA[b][r + 8][kw + tq + 4];
            }
#pragma unroll
            for (int nt = 0; nt < 4; nt++) {
                const int n = wn * 32 + nt * 8 + g;
                bf[nt][0] = smB[b][kw + tq    ][n];
                bf[nt][1] = smB[b][kw + tq + 4][n];
            }
#pragma unroll
            for (int mt = 0; mt < 2; mt++)
#pragma unroll
                for (int nt = 0; nt < 4; nt++)
                    mma_bf16(acc[mt][nt], af[mt], bf[nt]);
        }

        if (k0 + 1 < KIT2) {
            const int nb = b ^ 1;
#pragma unroll
            for (int i = 0; i < 2; i++)
                *(uint4*)&smA[nb][a_row + i * 64][a_c4 * 4] = pa[i];
            uint4 w;
            w.x = __byte_perm(pb0.x, pb1.x, 0x5410);
            w.y = __byte_perm(pb0.x, pb1.x, 0x7632);
            w.z = __byte_perm(pb0.y, pb1.y, 0x5410);
            w.w = __byte_perm(pb0.y, pb1.y, 0x7632);
            *(uint4*)&smB[nb][b_k2][b_n4] = w;
        }
        __syncthreads();
    }

#pragma unroll
    for (int mt = 0; mt < 2; mt++) {
        const int r0 = bm + wm * 32 + mt * 16 + g;
#pragma unroll
        for (int nt = 0; nt < 4; nt++) {
            const int cb = bn + wn * 32 + nt * 8 + tq * 2;
            const float b0 = bias[cb], b1 = bias[cb + 1];
            float2 o;
            o.x = fmaxf(acc[mt][nt][0] + b0, 0.f);
            o.y = fmaxf(acc[mt][nt][1] + b1, 0.f);
            *(float2*)(C + (size_t)r0 * HID + cb) = o;
            o.x = fmaxf(acc[mt][nt][2] + b0, 0.f);
            o.y = fmaxf(acc[mt][nt][3] + b1, 0.f);
            *(float2*)(C + (size_t)(r0 + 8) * HID + cb) = o;
        }
    }
}

// ---------------- edge scatter: half-warp per edge, vector red ----------------
__global__ void k_scatter(const int* __restrict__ src, const int* __restrict__ dst) {
    int gt = blockIdx.x * blockDim.x + threadIdx.x;
    int e  = gt >> 4;
    int l  = gt & 15;
    if (e >= EE) return;
    int s = src[e];
    int d = dst[e];
    float norm = g_dinv[s] * g_dinv[d];
    float4 v = *(const float4*)&g_h[(size_t)s * DD + l * 4];
    float* o = &g_h2[(size_t)d * DD + l * 4];
    asm volatile("red.global.add.v4.f32 [%0], {%1, %2, %3, %4};"
                 :: "l"(o), "f"(v.x * norm), "f"(v.y * norm),
                    "f"(v.z * norm), "f"(v.w * norm)
                 : "memory");
}

// ---------------- bias + relu + bf16 convert ----------------
__global__ void k_bias_relu_cvt(const float* __restrict__ bc) {
    size_t i4 = ((size_t)blockIdx.x * blockDim.x + threadIdx.x) * 4;
    if (i4 >= (size_t)NN * DD) return;
    float4 v = *(const float4*)(g_h2 + i4);
    int c = (int)(i4 & 63);
    float r0 = fmaxf(v.x + bc[c],     0.f);
    float r1 = fmaxf(v.y + bc[c + 1], 0.f);
    float r2 = fmaxf(v.z + bc[c + 2], 0.f);
    float r3 = fmaxf(v.w + bc[c + 3], 0.f);
    uint2 o;
    o.x = ((uint32_t)__bfloat16_as_ushort(__float2bfloat16(r0)))
        | ((uint32_t)__bfloat16_as_ushort(__float2bfloat16(r1)) << 16);
    o.y = ((uint32_t)__bfloat16_as_ushort(__float2bfloat16(r2)))
        | ((uint32_t)__bfloat16_as_ushort(__float2bfloat16(r3)) << 16);
    *(uint2*)(g_h2b + i4) = o;
}

// ---------------- head: logits = o1 @ W2 + b2, softmax ----------------
__global__ void k_head(const float* __restrict__ W2, const float* __restrict__ b2,
                       float* __restrict__ out) {
    int warp = (blockIdx.x * blockDim.x + threadIdx.x) >> 5;
    int lane = threadIdx.x & 31;
    if (warp >= NB) return;
    const float* row = &g_o1[(size_t)warp * HID];
    float s0 = 0.f, s1 = 0.f;
    for (int j = lane; j < HID; j += 32) {
        float v = row[j];
        s0 = fmaf(v, W2[j * 2 + 0], s0);
        s1 = fmaf(v, W2[j * 2 + 1], s1);
    }
#pragma unroll
    for (int off = 16; off > 0; off >>= 1) {
        s0 += __shfl_down_sync(0xffffffffu, s0, off);
        s1 += __shfl_down_sync(0xffffffffu, s1, off);
    }
    if (lane == 0) {
        float l0 = s0 + b2[0];
        float l1 = s1 + b2[1];
        float m  = fmaxf(l0, l1);
        float e0 = expf(l0 - m);
        float e1 = expf(l1 - m);
        float inv = 1.f / (e0 + e1);
        out[warp * 2 + 0] = e0 * inv;
        out[warp * 2 + 1] = e1 * inv;
    }
}

// ---------------- launch ----------------
extern "C" void kernel_launch(void* const* d_in, const int* in_sizes, int n_in,
                              void* d_out, int out_size) {
    const float* x  = (const float*)d_in[0];
    const int*   ei = (const int*)  d_in[1];
    const float* Wc = (const float*)d_in[3];
    const float* bc = (const float*)d_in[4];
    const float* W1 = (const float*)d_in[5];
    const float* b1 = (const float*)d_in[6];
    const float* W2 = (const float*)d_in[7];
    const float* b2 = (const float*)d_in[8];
    float* out = (float*)d_out;

    float *ph, *ph2, *po1, *pdinv;
    __nv_bfloat16 *ph2b, *pW1b;
    cudaGetSymbolAddress((void**)&ph,   g_h);
    cudaGetSymbolAddress((void**)&ph2,  g_h2);
    cudaGetSymbolAddress((void**)&po1,  g_o1);
    cudaGetSymbolAddress((void**)&pdinv, g_dinv);
    cudaGetSymbolAddress((void**)&ph2b, g_h2b);
    cudaGetSymbolAddress((void**)&pW1b, g_W1b);

    static int smem_set = 0;
    if (!smem_set) {
        cudaFuncSetAttribute(k_gemm_conv<DD, DD, DD / BK>,
                             cudaFuncAttributeMaxDynamicSharedMemorySize, SM_TOTAL_B);
        smem_set = 1;
    }

    const int* src = ei;        // edge_index[0]
    const int* dst = ei + EE;   // edge_index[1]

    // degrees (needed by conv epilogue)
    k_deg_init <<<(NN + 255) / 256, 256>>>();
    k_deg_count<<<(EE + 255) / 256, 256>>>(dst);
    k_dinv     <<<(NN + 255) / 256, 256>>>();

    // W1 -> bf16 (independent; any time before big GEMM)
    k_cvt_w1<<<((size_t)HID * HID / 4 + 255) / 256, 256>>>(W1);

    // h = x @ W_conv ; h2 = h * dinv^2 (fused self-loop init)
    {
        dim3 grid(DD / BN, NN / BM);
        k_gemm_conv<DD, DD, DD / BK>
            <<<grid, 256, SM_TOTAL_B>>>(x, Wc, ph, ph2, pdinv);
    }

    // scatter edges, then bias+relu+cvt -> bf16
    k_scatter      <<<((size_t)EE * 16 + 255) / 256, 256>>>(src, dst);
    k_bias_relu_cvt<<<((size_t)NN * DD / 4 + 255) / 256, 256>>>(bc);

    // o1 = relu(H @ W1 + b1)   — bf16 mma
    {
        dim3 grid(HID / BN, NB / BM);
        k_gemm_bf16<<<grid, 256>>>(ph2b, pW1b, po1, b1);
    }

    // logits + softmax
    k_head<<<(NB * 32 + 255) / 256, 256>>>(W2, b2, out);
}

// round 6
// speedup vs baseline: 3.5326x; 1.2329x over previous
#include <cuda_runtime.h>
#include <cuda_bf16.h>
#include <math.h>
#include <stdint.h>

#define NN   204800      // total nodes
#define DD   64          // embed dim
#define EE   3276800     // edges
#define NB   8192        // graphs
#define HID  1600        // 25 * 64
#define NBLK 200         // NN / 1024 scan blocks

// GEMM tiling
#define BM 128
#define BN 64
#define BK 32

// ---- tf32 conv kernel smem (dynamic) ----
#define ASTRIDE 44
#define BSTRIDE 72
#define A_BUF_F (BM * ASTRIDE)
#define B_BUF_F (BK * BSTRIDE)
#define SM_B_BASE (2 * A_BUF_F)
#define SM_TOTAL_B ((2 * A_BUF_F + 2 * B_BUF_F) * 4)

// ---- bf16 kernel smem strides (uint32 words) ----
#define ASTR2 20
#define BSTR2 72

// ---------------- scratch (device globals; no allocation) ----------------
__device__ int   g_deg[NN];          // edge-only in-degree
__device__ float g_dinv[NN];         // rsqrt(deg + 1)
__device__ int   g_off[NN + 1];      // CSR offsets
__device__ int   g_cur[NN];          // fill cursors
__device__ int   g_bsum[NBLK];
__device__ int   g_bscan[NBLK];
__device__ int   g_csr[EE];          // src ids grouped by dst
__device__ float g_hs [(size_t)NN * DD];           // (x @ W_conv) * dinv[row]
__device__ __nv_bfloat16 g_h2b[(size_t)NN * DD];   // relu(agg + bc) bf16
__device__ __nv_bfloat16 g_W1b[(size_t)HID * HID]; // W1 bf16
__device__ float g_o1[(size_t)NB * HID];           // relu(H @ W1 + b1)

// ---------------- degree ----------------
__global__ void k_deg_init() {
    int i = blockIdx.x * blockDim.x + threadIdx.x;
    if (i < NN) g_deg[i] = 0;
}
__global__ void k_deg_count(const int* __restrict__ dst) {
    int e = blockIdx.x * blockDim.x + threadIdx.x;
    if (e < EE) atomicAdd(&g_deg[dst[e]], 1);
}
__global__ void k_dinv() {
    int i = blockIdx.x * blockDim.x + threadIdx.x;
    if (i < NN) g_dinv[i] = rsqrtf((float)(g_deg[i] + 1));
}

// ---------------- exclusive scan of g_deg -> g_off ----------------
__global__ __launch_bounds__(1024)
void k_scan1() {
    __shared__ int sh[1024];
    int i = blockIdx.x * 1024 + threadIdx.x;
    int v = g_deg[i];
    sh[threadIdx.x] = v;
    __syncthreads();
#pragma unroll
    for (int off = 1; off < 1024; off <<= 1) {
        int t = (threadIdx.x >= off) ? sh[threadIdx.x - off] : 0;
        __syncthreads();
        sh[threadIdx.x] += t;
        __syncthreads();
    }
    g_off[i] = sh[threadIdx.x] - v;     // exclusive within block
    g_cur[i] = 0;
    if (threadIdx.x == 1023) g_bsum[blockIdx.x] = sh[1023];
}
__global__ void k_scan2() {
    if (threadIdx.x == 0) {
        int acc = 0;
        for (int b = 0; b < NBLK; b++) { g_bscan[b] = acc; acc += g_bsum[b]; }
        g_off[NN] = acc;                // == EE
    }
}
__global__ __launch_bounds__(1024)
void k_scan3() {
    int i = blockIdx.x * 1024 + threadIdx.x;
    g_off[i] += g_bscan[blockIdx.x];
}

// ---------------- CSR fill ----------------
__global__ void k_fill(const int* __restrict__ src, const int* __restrict__ dst) {
    int e = blockIdx.x * blockDim.x + threadIdx.x;
    if (e >= EE) return;
    int d = dst[e];
    int slot = atomicAdd(&g_cur[d], 1);
    g_csr[g_off[d] + slot] = src[e];
}

// ---------------- W1 -> bf16 ----------------
__global__ void k_cvt_w1(const float* __restrict__ W1) {
    size_t i4 = ((size_t)blockIdx.x * blockDim.x + threadIdx.x) * 4;
    if (i4 >= (size_t)HID * HID) return;
    float4 v = *(const float4*)(W1 + i4);
    uint2 o;
    o.x = ((uint32_t)__bfloat16_as_ushort(__float2bfloat16(v.x)))
        | ((uint32_t)__bfloat16_as_ushort(__float2bfloat16(v.y)) << 16);
    o.y = ((uint32_t)__bfloat16_as_ushort(__float2bfloat16(v.z)))
        | ((uint32_t)__bfloat16_as_ushort(__float2bfloat16(v.w)) << 16);
    *(uint2*)(g_W1b + i4) = o;
}

// ================= tf32 mma.sync GEMM (conv): hs = (A @ B) * dinv[row] ========
__device__ __forceinline__ uint32_t f2tf(float f) {
    uint32_t u;
    asm("cvt.rna.tf32.f32 %0, %1;" : "=r"(u) : "f"(f));
    return u;
}
__device__ __forceinline__ void mma_tf32(float* c, const uint32_t* a, const uint32_t* b) {
    asm volatile(
        "mma.sync.aligned.m16n8k8.row.col.f32.tf32.tf32.f32 "
        "{%0,%1,%2,%3}, {%4,%5,%6,%7}, {%8,%9}, {%0,%1,%2,%3};"
        : "+f"(c[0]), "+f"(c[1]), "+f"(c[2]), "+f"(c[3])
        : "r"(a[0]), "r"(a[1]), "r"(a[2]), "r"(a[3]), "r"(b[0]), "r"(b[1]));
}

template<int KTOT, int NTOT, int KIT>
__global__ __launch_bounds__(256, 2)
void k_gemm_conv(const float* __restrict__ A, const float* __restrict__ B,
                 float* __restrict__ C, const float* __restrict__ dinv) {
    extern __shared__ float sm[];
#define AS_(b, r, c) sm[(b) * A_BUF_F + (r) * ASTRIDE + (c)]
#define BS_(b, k, n) sm[SM_B_BASE + (b) * B_BUF_F + (k) * BSTRIDE + (n)]

    const int tid = threadIdx.x;
    const int wid = tid >> 5;
    const int lid = tid & 31;
    const int g   = lid >> 2;
    const int tq  = lid & 3;
    const int wm  = wid >> 1;
    const int wn  = wid & 1;
    const int bm  = blockIdx.y * BM;
    const int bn  = blockIdx.x * BN;

    const float* Ag = A + (size_t)bm * KTOT;
    const float* Bg = B + bn;

    float acc[2][4][4];
#pragma unroll
    for (int mt = 0; mt < 2; mt++)
#pragma unroll
        for (int nt = 0; nt < 4; nt++)
#pragma unroll
            for (int j = 0; j < 4; j++) acc[mt][nt][j] = 0.f;

    const int a_row = tid >> 3;
    const int a_c4  = (tid & 7) * 4;
    const int b_row = tid >> 4;
    const int b_c4  = (tid & 15) * 4;

    float4 pa[4], pb[2];
#pragma unroll
    for (int i = 0; i < 4; i++)
        pa[i] = *(const float4*)(Ag + (size_t)(a_row + i * 32) * KTOT + a_c4);
#pragma unroll
    for (int i = 0; i < 2; i++)
        pb[i] = *(const float4*)(Bg + (size_t)(b_row + i * 16) * NTOT + b_c4);
#pragma unroll
    for (int i = 0; i < 4; i++) {
        uint4 t = make_uint4(f2tf(pa[i].x), f2tf(pa[i].y), f2tf(pa[i].z), f2tf(pa[i].w));
        *(uint4*)&AS_(0, a_row + i * 32, a_c4) = t;
    }
#pragma unroll
    for (int i = 0; i < 2; i++) {
        uint4 t = make_uint4(f2tf(pb[i].x), f2tf(pb[i].y), f2tf(pb[i].z), f2tf(pb[i].w));
        *(uint4*)&BS_(0, b_row + i * 16, b_c4) = t;
    }
    __syncthreads();

    for (int k0 = 0; k0 < KIT; k0++) {
        const int b = k0 & 1;
        if (k0 + 1 < KIT) {
            const float* An = Ag + (k0 + 1) * BK;
            const float* Bn = Bg + (size_t)(k0 + 1) * BK * NTOT;
#pragma unroll
            for (int i = 0; i < 4; i++)
                pa[i] = *(const float4*)(An + (size_t)(a_row + i * 32) * KTOT + a_c4);
#pragma unroll
            for (int i = 0; i < 2; i++)
                pb[i] = *(const float4*)(Bn + (size_t)(b_row + i * 16) * NTOT + b_c4);
        }
#pragma unroll
        for (int ks = 0; ks < 4; ks++) {
            const int kb = ks * 8;
            uint32_t af[2][4], bf[4][2];
#pragma unroll
            for (int mt = 0; mt < 2; mt++) {
                const int r = wm * 32 + mt * 16 + g;
                af[mt][0] = __float_as_uint(AS_(b, r,     kb + tq));
                af[mt][1] = __float_as_uint(AS_(b, r + 8, kb + tq));
                af[mt][2] = __float_as_uint(AS_(b, r,     kb + tq + 4));
                af[mt][3] = __float_as_uint(AS_(b, r + 8, kb + tq + 4));
            }
#pragma unroll
            for (int nt = 0; nt < 4; nt++) {
                const int n = wn * 32 + nt * 8 + g;
                bf[nt][0] = __float_as_uint(BS_(b, kb + tq,     n));
                bf[nt][1] = __float_as_uint(BS_(b, kb + tq + 4, n));
            }
#pragma unroll
            for (int mt = 0; mt < 2; mt++)
#pragma unroll
                for (int nt = 0; nt < 4; nt++)
                    mma_tf32(acc[mt][nt], af[mt], bf[nt]);
        }
        if (k0 + 1 < KIT) {
            const int nb = b ^ 1;
#pragma unroll
            for (int i = 0; i < 4; i++) {
                uint4 t = make_uint4(f2tf(pa[i].x), f2tf(pa[i].y), f2tf(pa[i].z), f2tf(pa[i].w));
                *(uint4*)&AS_(nb, a_row + i * 32, a_c4) = t;
            }
#pragma unroll
            for (int i = 0; i < 2; i++) {
                uint4 t = make_uint4(f2tf(pb[i].x), f2tf(pb[i].y), f2tf(pb[i].z), f2tf(pb[i].w));
                *(uint4*)&BS_(nb, b_row + i * 16, b_c4) = t;
            }
        }
        __syncthreads();
    }

#pragma unroll
    for (int mt = 0; mt < 2; mt++) {
        const int r0 = bm + wm * 32 + mt * 16 + g;
        const float d0 = dinv[r0];
        const float d1 = dinv[r0 + 8];
#pragma unroll
        for (int nt = 0; nt < 4; nt++) {
            const int cb = bn + wn * 32 + nt * 8 + tq * 2;
            float2 o;
            o.x = acc[mt][nt][0] * d0; o.y = acc[mt][nt][1] * d0;
            *(float2*)(C + (size_t)r0 * NTOT + cb) = o;
            o.x = acc[mt][nt][2] * d1; o.y = acc[mt][nt][3] * d1;
            *(float2*)(C + (size_t)(r0 + 8) * NTOT + cb) = o;
        }
    }
#undef AS_
#undef BS_
}

// ---------------- CSR aggregate: warp per node ----------------
// h2b[d] = bf16(relu(dinv[d] * (hs[d] + sum_{s in CSR[d]} hs[s]) + bc))
__global__ __launch_bounds__(256)
void k_aggregate(const float* __restrict__ bc) {
    const int node = blockIdx.x * 8 + (threadIdx.x >> 5);
    const int lane = threadIdx.x & 31;
    const int c2   = lane * 2;

    float2 acc = *(const float2*)&g_hs[(size_t)node * DD + c2];   // self loop
    const int beg = g_off[node];
    const int end = g_off[node + 1];

    int i = beg;
    for (; i + 1 < end; i += 2) {
        int s0 = g_csr[i];
        int s1 = g_csr[i + 1];
        float2 v0 = *(const float2*)&g_hs[(size_t)s0 * DD + c2];
        float2 v1 = *(const float2*)&g_hs[(size_t)s1 * DD + c2];
        acc.x += v0.x + v1.x;
        acc.y += v0.y + v1.y;
    }
    if (i < end) {
        int s = g_csr[i];
        float2 v = *(const float2*)&g_hs[(size_t)s * DD + c2];
        acc.x += v.x;
        acc.y += v.y;
    }

    const float sc = g_dinv[node];
    float r0 = fmaxf(acc.x * sc + bc[c2],     0.f);
    float r1 = fmaxf(acc.y * sc + bc[c2 + 1], 0.f);
    uint32_t o = ((uint32_t)__bfloat16_as_ushort(__float2bfloat16(r0)))
               | ((uint32_t)__bfloat16_as_ushort(__float2bfloat16(r1)) << 16);
    *(uint32_t*)(g_h2b + (size_t)node * DD + c2) = o;
}

// ================= bf16 mma.sync GEMM (dense head) =================
__device__ __forceinline__ void mma_bf16(float* c, const uint32_t* a, const uint32_t* b) {
    asm volatile(
        "mma.sync.aligned.m16n8k16.row.col.f32.bf16.bf16.f32 "
        "{%0,%1,%2,%3}, {%4,%5,%6,%7}, {%8,%9}, {%0,%1,%2,%3};"
        : "+f"(c[0]), "+f"(c[1]), "+f"(c[2]), "+f"(c[3])
        : "r"(a[0]), "r"(a[1]), "r"(a[2]), "r"(a[3]), "r"(b[0]), "r"(b[1]));
}

#define KIT2 (HID / BK)     // 50
__global__ __launch_bounds__(256, 2)
void k_gemm_bf16(const __nv_bfloat16* __restrict__ A, const __nv_bfloat16* __restrict__ B,
                 float* __restrict__ C, const float* __restrict__ bias) {
    __shared__ uint32_t smA[2][BM][ASTR2];
    __shared__ uint32_t smB[2][BK / 2][BSTR2];

    const int tid = threadIdx.x;
    const int wid = tid >> 5;
    const int lid = tid & 31;
    const int g   = lid >> 2;
    const int tq  = lid & 3;
    const int wm  = wid >> 1;
    const int wn  = wid & 1;
    const int bm  = blockIdx.y * BM;
    const int bn  = blockIdx.x * BN;

    const __nv_bfloat16* Ag = A + (size_t)bm * HID;
    const __nv_bfloat16* Bg = B + bn;

    float acc[2][4][4];
#pragma unroll
    for (int mt = 0; mt < 2; mt++)
#pragma unroll
        for (int nt = 0; nt < 4; nt++)
#pragma unroll
            for (int j = 0; j < 4; j++) acc[mt][nt][j] = 0.f;

    const int a_row = tid >> 2;
    const int a_c4  = tid & 3;
    const int b_k2  = tid >> 4;
    const int b_n4  = (tid & 15) * 4;

    uint4 pa[2];
    uint2 pb0, pb1;

#pragma unroll
    for (int i = 0; i < 2; i++)
        pa[i] = *(const uint4*)(Ag + (size_t)(a_row + i * 64) * HID + a_c4 * 8);
    pb0 = *(const uint2*)(Bg + (size_t)(2 * b_k2)     * HID + b_n4);
    pb1 = *(const uint2*)(Bg + (size_t)(2 * b_k2 + 1) * HID + b_n4);
#pragma unroll
    for (int i = 0; i < 2; i++)
        *(uint4*)&smA[0][a_row + i * 64][a_c4 * 4] = pa[i];
    {
        uint4 w;
        w.x = __byte_perm(pb0.x, pb1.x, 0x5410);
        w.y = __byte_perm(pb0.x, pb1.x, 0x7632);
        w.z = __byte_perm(pb0.y, pb1.y, 0x5410);
        w.w = __byte_perm(pb0.y, pb1.y, 0x7632);
        *(uint4*)&smB[0][b_k2][b_n4] = w;
    }
    __syncthreads();

    for (int k0 = 0; k0 < KIT2; k0++) {
        const int b = k0 & 1;
        if (k0 + 1 < KIT2) {
            const __nv_bfloat16* An = Ag + (k0 + 1) * BK;
            const __nv_bfloat16* Bn = Bg + (size_t)(k0 + 1) * BK * HID;
#pragma unroll
            for (int i = 0; i < 2; i++)
                pa[i] = *(const uint4*)(An + (size_t)(a_row + i * 64) * HID + a_c4 * 8);
            pb0 = *(const uint2*)(Bn + (size_t)(2 * b_k2)     * HID + b_n4);
            pb1 = *(const uint2*)(Bn + (size_t)(2 * b_k2 + 1) * HID + b_n4);
        }

#pragma unroll
        for (int ks = 0; ks < 2; ks++) {
            const int kw = ks * 8;
            uint32_t af[2][4], bf[4][2];
#pragma unroll
            for (int mt = 0; mt < 2; mt++) {
                const int r = wm * 32 + mt * 16 + g;
                af[mt][0] = smA[b][r    ][kw + tq];
                af[mt][1] = smA[b][r + 8][kw + tq];
                af[mt][2] = smA[b][r    ][kw + tq + 4];
                af[mt][3] = smA[b][r + 8][kw + tq + 4];
            }
#pragma unroll
            for (int nt = 0; nt < 4; nt++) {
                const int n = wn * 32 + nt * 8 + g;
                bf[nt][0] = smB[b][kw + tq    ][n];
                bf[nt][1] = smB[b][kw + tq + 4][n];
            }
#pragma unroll
            for (int mt = 0; mt < 2; mt++)
#pragma unroll
                for (int nt = 0; nt < 4; nt++)
                    mma_bf16(acc[mt][nt], af[mt], bf[nt]);
        }

        if (k0 + 1 < KIT2) {
            const int nb = b ^ 1;
#pragma unroll
            for (int i = 0; i < 2; i++)
                *(uint4*)&smA[nb][a_row + i * 64][a_c4 * 4] = pa[i];
            uint4 w;
            w.x = __byte_perm(pb0.x, pb1.x, 0x5410);
            w.y = __byte_perm(pb0.x, pb1.x, 0x7632);
            w.z = __byte_perm(pb0.y, pb1.y, 0x5410);
            w.w = __byte_perm(pb0.y, pb1.y, 0x7632);
            *(uint4*)&smB[nb][b_k2][b_n4] = w;
        }
        __syncthreads();
    }

#pragma unroll
    for (int mt = 0; mt < 2; mt++) {
        const int r0 = bm + wm * 32 + mt * 16 + g;
#pragma unroll
        for (int nt = 0; nt < 4; nt++) {
            const int cb = bn + wn * 32 + nt * 8 + tq * 2;
            const float b0 = bias[cb], b1 = bias[cb + 1];
            float2 o;
            o.x = fmaxf(acc[mt][nt][0] + b0, 0.f);
            o.y = fmaxf(acc[mt][nt][1] + b1, 0.f);
            *(float2*)(C + (size_t)r0 * HID + cb) = o;
            o.x = fmaxf(acc[mt][nt][2] + b0, 0.f);
            o.y = fmaxf(acc[mt][nt][3] + b1, 0.f);
            *(float2*)(C + (size_t)(r0 + 8) * HID + cb) = o;
        }
    }
}

// ---------------- head: logits = o1 @ W2 + b2, softmax ----------------
__global__ void k_head(const float* __restrict__ W2, const float* __restrict__ b2,
                       float* __restrict__ out) {
    int warp = (blockIdx.x * blockDim.x + threadIdx.x) >> 5;
    int lane = threadIdx.x & 31;
    if (warp >= NB) return;
    const float* row = &g_o1[(size_t)warp * HID];
    float s0 = 0.f, s1 = 0.f;
    for (int j = lane; j < HID; j += 32) {
        float v = row[j];
        s0 = fmaf(v, W2[j * 2 + 0], s0);
        s1 = fmaf(v, W2[j * 2 + 1], s1);
    }
#pragma unroll
    for (int off = 16; off > 0; off >>= 1) {
        s0 += __shfl_down_sync(0xffffffffu, s0, off);
        s1 += __shfl_down_sync(0xffffffffu, s1, off);
    }
    if (lane == 0) {
        float l0 = s0 + b2[0];
        float l1 = s1 + b2[1];
        float m  = fmaxf(l0, l1);
        float e0 = expf(l0 - m);
        float e1 = expf(l1 - m);
        float inv = 1.f / (e0 + e1);
        out[warp * 2 + 0] = e0 * inv;
        out[warp * 2 + 1] = e1 * inv;
    }
}

// ---------------- launch ----------------
extern "C" void kernel_launch(void* const* d_in, const int* in_sizes, int n_in,
                              void* d_out, int out_size) {
    const float* x  = (const float*)d_in[0];
    const int*   ei = (const int*)  d_in[1];
    const float* Wc = (const float*)d_in[3];
    const float* bc = (const float*)d_in[4];
    const float* W1 = (const float*)d_in[5];
    const float* b1 = (const float*)d_in[6];
    const float* W2 = (const float*)d_in[7];
    const float* b2 = (const float*)d_in[8];
    float* out = (float*)d_out;

    float *phs, *po1, *pdinv;
    __nv_bfloat16 *ph2b, *pW1b;
    cudaGetSymbolAddress((void**)&phs,  g_hs);
    cudaGetSymbolAddress((void**)&po1,  g_o1);
    cudaGetSymbolAddress((void**)&pdinv, g_dinv);
    cudaGetSymbolAddress((void**)&ph2b, g_h2b);
    cudaGetSymbolAddress((void**)&pW1b, g_W1b);

    static int smem_set = 0;
    if (!smem_set) {
        cudaFuncSetAttribute(k_gemm_conv<DD, DD, DD / BK>,
                             cudaFuncAttributeMaxDynamicSharedMemorySize, SM_TOTAL_B);
        smem_set = 1;
    }

    const int* src = ei;        // edge_index[0]
    const int* dst = ei + EE;   // edge_index[1]

    // degrees + CSR offsets + fill
    k_deg_init <<<(NN + 255) / 256, 256>>>();
    k_deg_count<<<(EE + 255) / 256, 256>>>(dst);
    k_dinv     <<<(NN + 255) / 256, 256>>>();
    k_scan1    <<<NBLK, 1024>>>();
    k_scan2    <<<1, 32>>>();
    k_scan3    <<<NBLK, 1024>>>();
    k_fill     <<<(EE + 255) / 256, 256>>>(src, dst);

    // W1 -> bf16 (independent)
    k_cvt_w1<<<((size_t)HID * HID / 4 + 255) / 256, 256>>>(W1);

    // hs = (x @ W_conv) * dinv[row]
    {
        dim3 grid(DD / BN, NN / BM);
        k_gemm_conv<DD, DD, DD / BK>
            <<<grid, 256, SM_TOTAL_B>>>(x, Wc, phs, pdinv);
    }

    // CSR gather aggregate + bias + relu + bf16 cvt
    k_aggregate<<<NN / 8, 256>>>(bc);

    // o1 = relu(H @ W1 + b1) — bf16 mma
    {
        dim3 grid(HID / BN, NB / BM);
        k_gemm_bf16<<<grid, 256>>>(ph2b, pW1b, po1, b1);
    }

    // logits + softmax
    k_head<<<(NB * 32 + 255) / 256, 256>>>(W2, b2, out);
}

// round 7
// speedup vs baseline: 3.6954x; 1.0461x over previous
#include <cuda_runtime.h>
#include <cuda_bf16.h>
#include <cuda_fp16.h>
#include <math.h>
#include <stdint.h>

#define NN   204800      // total nodes
#define DD   64          // embed dim
#define EE   3276800     // edges
#define NB   8192        // graphs
#define HID  1600        // 25 * 64
#define NBLK 200         // NN / 1024 scan blocks

// GEMM tiling
#define BM 128
#define BN 64
#define BK 32

// ---- tf32 conv kernel smem (dynamic) ----
#define ASTRIDE 44
#define BSTRIDE 72
#define A_BUF_F (BM * ASTRIDE)
#define B_BUF_F (BK * BSTRIDE)
#define SM_B_BASE (2 * A_BUF_F)
#define SM_TOTAL_B ((2 * A_BUF_F + 2 * B_BUF_F) * 4)

// ---- bf16 kernel smem strides (uint32 words) ----
#define ASTR2 20
#define BSTR2 72

// ---------------- scratch (device globals; no allocation) ----------------
__device__ int   g_deg[NN];
__device__ float g_dinv[NN];
__device__ int   g_off[NN + 1];
__device__ int   g_cur[NN];
__device__ int   g_bsum[NBLK];
__device__ int   g_bscan[NBLK];
__device__ int   g_csr[EE];
__device__ __half g_hs[(size_t)NN * DD];           // (x @ W_conv) * dinv[row], fp16
__device__ __nv_bfloat16 g_h2b[(size_t)NN * DD];   // relu(agg + bc) bf16
__device__ __nv_bfloat16 g_W1b[(size_t)HID * HID]; // W1 bf16
__device__ float g_o1[(size_t)NB * HID];           // relu(H @ W1 + b1)

// ---------------- degree ----------------
__global__ void k_deg_init() {
    int i = blockIdx.x * blockDim.x + threadIdx.x;
    if (i < NN) g_deg[i] = 0;
}
__global__ void k_deg_count(const int* __restrict__ dst) {
    int e4 = (blockIdx.x * blockDim.x + threadIdx.x) * 4;
    if (e4 >= EE) return;
    int4 d = *(const int4*)(dst + e4);
    atomicAdd(&g_deg[d.x], 1);
    atomicAdd(&g_deg[d.y], 1);
    atomicAdd(&g_deg[d.z], 1);
    atomicAdd(&g_deg[d.w], 1);
}
__global__ void k_dinv() {
    int i = blockIdx.x * blockDim.x + threadIdx.x;
    if (i < NN) g_dinv[i] = rsqrtf((float)(g_deg[i] + 1));
}

// ---------------- exclusive scan of g_deg -> g_off ----------------
__global__ __launch_bounds__(1024)
void k_scan1() {
    __shared__ int sh[1024];
    int i = blockIdx.x * 1024 + threadIdx.x;
    int v = g_deg[i];
    sh[threadIdx.x] = v;
    __syncthreads();
#pragma unroll
    for (int off = 1; off < 1024; off <<= 1) {
        int t = (threadIdx.x >= off) ? sh[threadIdx.x - off] : 0;
        __syncthreads();
        sh[threadIdx.x] += t;
        __syncthreads();
    }
    g_off[i] = sh[threadIdx.x] - v;
    g_cur[i] = 0;
    if (threadIdx.x == 1023) g_bsum[blockIdx.x] = sh[1023];
}
__global__ void k_scan2() {
    if (threadIdx.x == 0) {
        int acc = 0;
        for (int b = 0; b < NBLK; b++) { g_bscan[b] = acc; acc += g_bsum[b]; }
        g_off[NN] = acc;
    }
}
__global__ __launch_bounds__(1024)
void k_scan3() {
    int i = blockIdx.x * 1024 + threadIdx.x;
    g_off[i] += g_bscan[blockIdx.x];
}

// ---------------- CSR fill (4 edges / thread) ----------------
__global__ void k_fill(const int* __restrict__ src, const int* __restrict__ dst) {
    int e4 = (blockIdx.x * blockDim.x + threadIdx.x) * 4;
    if (e4 >= EE) return;
    int4 d = *(const int4*)(dst + e4);
    int4 s = *(const int4*)(src + e4);
    g_csr[g_off[d.x] + atomicAdd(&g_cur[d.x], 1)] = s.x;
    g_csr[g_off[d.y] + atomicAdd(&g_cur[d.y], 1)] = s.y;
    g_csr[g_off[d.z] + atomicAdd(&g_cur[d.z], 1)] = s.z;
    g_csr[g_off[d.w] + atomicAdd(&g_cur[d.w], 1)] = s.w;
}

// ---------------- W1 -> bf16 ----------------
__global__ void k_cvt_w1(const float* __restrict__ W1) {
    size_t i4 = ((size_t)blockIdx.x * blockDim.x + threadIdx.x) * 4;
    if (i4 >= (size_t)HID * HID) return;
    float4 v = *(const float4*)(W1 + i4);
    uint2 o;
    o.x = ((uint32_t)__bfloat16_as_ushort(__float2bfloat16(v.x)))
        | ((uint32_t)__bfloat16_as_ushort(__float2bfloat16(v.y)) << 16);
    o.y = ((uint32_t)__bfloat16_as_ushort(__float2bfloat16(v.z)))
        | ((uint32_t)__bfloat16_as_ushort(__float2bfloat16(v.w)) << 16);
    *(uint2*)(g_W1b + i4) = o;
}

// ================= tf32 mma.sync GEMM (conv): hs = fp16((A @ B) * dinv[row]) ==
__device__ __forceinline__ uint32_t f2tf(float f) {
    uint32_t u;
    asm("cvt.rna.tf32.f32 %0, %1;" : "=r"(u) : "f"(f));
    return u;
}
__device__ __forceinline__ void mma_tf32(float* c, const uint32_t* a, const uint32_t* b) {
    asm volatile(
        "mma.sync.aligned.m16n8k8.row.col.f32.tf32.tf32.f32 "
        "{%0,%1,%2,%3}, {%4,%5,%6,%7}, {%8,%9}, {%0,%1,%2,%3};"
        : "+f"(c[0]), "+f"(c[1]), "+f"(c[2]), "+f"(c[3])
        : "r"(a[0]), "r"(a[1]), "r"(a[2]), "r"(a[3]), "r"(b[0]), "r"(b[1]));
}

template<int KTOT, int NTOT, int KIT>
__global__ __launch_bounds__(256, 2)
void k_gemm_conv(const float* __restrict__ A, const float* __restrict__ B,
                 __half* __restrict__ C, const float* __restrict__ dinv) {
    extern __shared__ float sm[];
#define AS_(b, r, c) sm[(b) * A_BUF_F + (r) * ASTRIDE + (c)]
#define BS_(b, k, n) sm[SM_B_BASE + (b) * B_BUF_F + (k) * BSTRIDE + (n)]

    const int tid = threadIdx.x;
    const int wid = tid >> 5;
    const int lid = tid & 31;
    const int g   = lid >> 2;
    const int tq  = lid & 3;
    const int wm  = wid >> 1;
    const int wn  = wid & 1;
    const int bm  = blockIdx.y * BM;
    const int bn  = blockIdx.x * BN;

    const float* Ag = A + (size_t)bm * KTOT;
    const float* Bg = B + bn;

    float acc[2][4][4];
#pragma unroll
    for (int mt = 0; mt < 2; mt++)
#pragma unroll
        for (int nt = 0; nt < 4; nt++)
#pragma unroll
            for (int j = 0; j < 4; j++) acc[mt][nt][j] = 0.f;

    const int a_row = tid >> 3;
    const int a_c4  = (tid & 7) * 4;
    const int b_row = tid >> 4;
    const int b_c4  = (tid & 15) * 4;

    float4 pa[4], pb[2];
#pragma unroll
    for (int i = 0; i < 4; i++)
        pa[i] = *(const float4*)(Ag + (size_t)(a_row + i * 32) * KTOT + a_c4);
#pragma unroll
    for (int i = 0; i < 2; i++)
        pb[i] = *(const float4*)(Bg + (size_t)(b_row + i * 16) * NTOT + b_c4);
#pragma unroll
    for (int i = 0; i < 4; i++) {
        uint4 t = make_uint4(f2tf(pa[i].x), f2tf(pa[i].y), f2tf(pa[i].z), f2tf(pa[i].w));
        *(uint4*)&AS_(0, a_row + i * 32, a_c4) = t;
    }
#pragma unroll
    for (int i = 0; i < 2; i++) {
        uint4 t = make_uint4(f2tf(pb[i].x), f2tf(pb[i].y), f2tf(pb[i].z), f2tf(pb[i].w));
        *(uint4*)&BS_(0, b_row + i * 16, b_c4) = t;
    }
    __syncthreads();

    for (int k0 = 0; k0 < KIT; k0++) {
        const int b = k0 & 1;
        if (k0 + 1 < KIT) {
            const float* An = Ag + (k0 + 1) * BK;
            const float* Bn = Bg + (size_t)(k0 + 1) * BK * NTOT;
#pragma unroll
            for (int i = 0; i < 4; i++)
                pa[i] = *(const float4*)(An + (size_t)(a_row + i * 32) * KTOT + a_c4);
#pragma unroll
            for (int i = 0; i < 2; i++)
                pb[i] = *(const float4*)(Bn + (size_t)(b_row + i * 16) * NTOT + b_c4);
        }
#pragma unroll
        for (int ks = 0; ks < 4; ks++) {
            const int kb = ks * 8;
            uint32_t af[2][4], bf[4][2];
#pragma unroll
            for (int mt = 0; mt < 2; mt++) {
                const int r = wm * 32 + mt * 16 + g;
                af[mt][0] = __float_as_uint(AS_(b, r,     kb + tq));
                af[mt][1] = __float_as_uint(AS_(b, r + 8, kb + tq));
                af[mt][2] = __float_as_uint(AS_(b, r,     kb + tq + 4));
                af[mt][3] = __float_as_uint(AS_(b, r + 8, kb + tq + 4));
            }
#pragma unroll
            for (int nt = 0; nt < 4; nt++) {
                const int n = wn * 32 + nt * 8 + g;
                bf[nt][0] = __float_as_uint(BS_(b, kb + tq,     n));
                bf[nt][1] = __float_as_uint(BS_(b, kb + tq + 4, n));
            }
#pragma unroll
            for (int mt = 0; mt < 2; mt++)
#pragma unroll
                for (int nt = 0; nt < 4; nt++)
                    mma_tf32(acc[mt][nt], af[mt], bf[nt]);
        }
        if (k0 + 1 < KIT) {
            const int nb = b ^ 1;
#pragma unroll
            for (int i = 0; i < 4; i++) {
                uint4 t = make_uint4(f2tf(pa[i].x), f2tf(pa[i].y), f2tf(pa[i].z), f2tf(pa[i].w));
                *(uint4*)&AS_(nb, a_row + i * 32, a_c4) = t;
            }
#pragma unroll
            for (int i = 0; i < 2; i++) {
                uint4 t = make_uint4(f2tf(pb[i].x), f2tf(pb[i].y), f2tf(pb[i].z), f2tf(pb[i].w));
                *(uint4*)&BS_(nb, b_row + i * 16, b_c4) = t;
            }
        }
        __syncthreads();
    }

#pragma unroll
    for (int mt = 0; mt < 2; mt++) {
        const int r0 = bm + wm * 32 + mt * 16 + g;
        const float d0 = dinv[r0];
        const float d1 = dinv[r0 + 8];
#pragma unroll
        for (int nt = 0; nt < 4; nt++) {
            const int cb = bn + wn * 32 + nt * 8 + tq * 2;
            __half2 h0 = __floats2half2_rn(acc[mt][nt][0] * d0, acc[mt][nt][1] * d0);
            *(__half2*)(C + (size_t)r0 * NTOT + cb) = h0;
            __half2 h1 = __floats2half2_rn(acc[mt][nt][2] * d1, acc[mt][nt][3] * d1);
            *(__half2*)(C + (size_t)(r0 + 8) * NTOT + cb) = h1;
        }
    }
#undef AS_
#undef BS_
}

// ---------------- CSR aggregate: warp per node (fp16 gather, fp32 acc) -------
// h2b[d] = bf16(relu(dinv[d] * (hs[d] + sum_{s in CSR[d]} hs[s]) + bc))
__global__ __launch_bounds__(256)
void k_aggregate(const float* __restrict__ bc) {
    const int node = blockIdx.x * 8 + (threadIdx.x >> 5);
    const int lane = threadIdx.x & 31;

    const __half2* hs2 = (const __half2*)g_hs;   // DD/2 = 32 half2 per row
    float2 acc;
    {
        float2 v = __half22float2(hs2[(size_t)node * 32 + lane]);
        acc.x = v.x; acc.y = v.y;
    }
    const int beg = g_off[node];
    const int end = g_off[node + 1];

    int i = beg;
    for (; i + 1 < end; i += 2) {
        int s0 = g_csr[i];
        int s1 = g_csr[i + 1];
        float2 v0 = __half22float2(hs2[(size_t)s0 * 32 + lane]);
        float2 v1 = __half22float2(hs2[(size_t)s1 * 32 + lane]);
        acc.x += v0.x + v1.x;
        acc.y += v0.y + v1.y;
    }
    if (i < end) {
        float2 v = __half22float2(hs2[(size_t)g_csr[i] * 32 + lane]);
        acc.x += v.x;
        acc.y += v.y;
    }

    const float sc = g_dinv[node];
    const int c2 = lane * 2;
    float r0 = fmaxf(acc.x * sc + bc[c2],     0.f);
    float r1 = fmaxf(acc.y * sc + bc[c2 + 1], 0.f);
    uint32_t o = ((uint32_t)__bfloat16_as_ushort(__float2bfloat16(r0)))
               | ((uint32_t)__bfloat16_as_ushort(__float2bfloat16(r1)) << 16);
    *(uint32_t*)(g_h2b + (size_t)node * DD + c2) = o;
}

// ================= bf16 mma.sync GEMM (dense head) =================
__device__ __forceinline__ void mma_bf16(float* c, const uint32_t* a, const uint32_t* b) {
    asm volatile(
        "mma.sync.aligned.m16n8k16.row.col.f32.bf16.bf16.f32 "
        "{%0,%1,%2,%3}, {%4,%5,%6,%7}, {%8,%9}, {%0,%1,%2,%3};"
        : "+f"(c[0]), "+f"(c[1]), "+f"(c[2]), "+f"(c[3])
        : "r"(a[0]), "r"(a[1]), "r"(a[2]), "r"(a[3]), "r"(b[0]), "r"(b[1]));
}

#define KIT2 (HID / BK)     // 50
__global__ __launch_bounds__(256, 2)
void k_gemm_bf16(const __nv_bfloat16* __restrict__ A, const __nv_bfloat16* __restrict__ B,
                 float* __restrict__ C, const float* __restrict__ bias) {
    __shared__ uint32_t smA[2][BM][ASTR2];
    __shared__ uint32_t smB[2][BK / 2][BSTR2];

    const int tid = threadIdx.x;
    const int wid = tid >> 5;
    const int lid = tid & 31;
    const int g   = lid >> 2;
    const int tq  = lid & 3;
    const int wm  = wid >> 1;
    const int wn  = wid & 1;
    const int bm  = blockIdx.y * BM;
    const int bn  = blockIdx.x * BN;

    const __nv_bfloat16* Ag = A + (size_t)bm * HID;
    const __nv_bfloat16* Bg = B + bn;

    float acc[2][4][4];
#pragma unroll
    for (int mt = 0; mt < 2; mt++)
#pragma unroll
        for (int nt = 0; nt < 4; nt++)
#pragma unroll
            for (int j = 0; j < 4; j++) acc[mt][nt][j] = 0.f;

    const int a_row = tid >> 2;
    const int a_c4  = tid & 3;
    const int b_k2  = tid >> 4;
    const int b_n4  = (tid & 15) * 4;

    uint4 pa[2];
    uint2 pb0, pb1;

#pragma unroll
    for (int i = 0; i < 2; i++)
        pa[i] = *(const uint4*)(Ag + (size_t)(a_row + i * 64) * HID + a_c4 * 8);
    pb0 = *(const uint2*)(Bg + (size_t)(2 * b_k2)     * HID + b_n4);
    pb1 = *(const uint2*)(Bg + (size_t)(2 * b_k2 + 1) * HID + b_n4);
#pragma unroll
    for (int i = 0; i < 2; i++)
        *(uint4*)&smA[0][a_row + i * 64][a_c4 * 4] = pa[i];
    {
        uint4 w;
        w.x = __byte_perm(pb0.x, pb1.x, 0x5410);
        w.y = __byte_perm(pb0.x, pb1.x, 0x7632);
        w.z = __byte_perm(pb0.y, pb1.y, 0x5410);
        w.w = __byte_perm(pb0.y, pb1.y, 0x7632);
        *(uint4*)&smB[0][b_k2][b_n4] = w;
    }
    __syncthreads();

    for (int k0 = 0; k0 < KIT2; k0++) {
        const int b = k0 & 1;
        if (k0 + 1 < KIT2) {
            const __nv_bfloat16* An = Ag + (k0 + 1) * BK;
            const __nv_bfloat16* Bn = Bg + (size_t)(k0 + 1) * BK * HID;
#pragma unroll
            for (int i = 0; i < 2; i++)
                pa[i] = *(const uint4*)(An + (size_t)(a_row + i * 64) * HID + a_c4 * 8);
            pb0 = *(const uint2*)(Bn + (size_t)(2 * b_k2)     * HID + b_n4);
            pb1 = *(const uint2*)(Bn + (size_t)(2 * b_k2 + 1) * HID + b_n4);
        }

#pragma unroll
        for (int ks = 0; ks < 2; ks++) {
            const int kw = ks * 8;
            uint32_t af[2][4], bf[4][2];
#pragma unroll
            for (int mt = 0; mt < 2; mt++) {
                const int r = wm * 32 + mt * 16 + g;
                af[mt][0] = smA[b][r    ][kw + tq];
                af[mt][1] = smA[b][r + 8][kw + tq];
                af[mt][2] = smA[b][r    ][kw + tq + 4];
                af[mt][3] = smA[b][r + 8][kw + tq + 4];
            }
#pragma unroll
            for (int nt = 0; nt < 4; nt++) {
                const int n = wn * 32 + nt * 8 + g;
                bf[nt][0] = smB[b][kw + tq    ][n];
                bf[nt][1] = smB[b][kw + tq + 4][n];
            }
#pragma unroll
            for (int mt = 0; mt < 2; mt++)
#pragma unroll
                for (int nt = 0; nt < 4; nt++)
                    mma_bf16(acc[mt][nt], af[mt], bf[nt]);
        }

        if (k0 + 1 < KIT2) {
            const int nb = b ^ 1;
#pragma unroll
            for (int i = 0; i < 2; i++)
                *(uint4*)&smA[nb][a_row + i * 64][a_c4 * 4] = pa[i];
            uint4 w;
            w.x = __byte_perm(pb0.x, pb1.x, 0x5410);
            w.y = __byte_perm(pb0.x, pb1.x, 0x7632);
            w.z = __byte_perm(pb0.y, pb1.y, 0x5410);
            w.w = __byte_perm(pb0.y, pb1.y, 0x7632);
            *(uint4*)&smB[nb][b_k2][b_n4] = w;
        }
        __syncthreads();
    }

#pragma unroll
    for (int mt = 0; mt < 2; mt++) {
        const int r0 = bm + wm * 32 + mt * 16 + g;
#pragma unroll
        for (int nt = 0; nt < 4; nt++) {
            const int cb = bn + wn * 32 + nt * 8 + tq * 2;
            const float b0 = bias[cb], b1 = bias[cb + 1];
            float2 o;
            o.x = fmaxf(acc[mt][nt][0] + b0, 0.f);
            o.y = fmaxf(acc[mt][nt][1] + b1, 0.f);
            *(float2*)(C + (size_t)r0 * HID + cb) = o;
            o.x = fmaxf(acc[mt][nt][2] + b0, 0.f);
            o.y = fmaxf(acc[mt][nt][3] + b1, 0.f);
            *(float2*)(C + (size_t)(r0 + 8) * HID + cb) = o;
        }
    }
}

// ---------------- head: logits = o1 @ W2 + b2, softmax ----------------
__global__ void k_head(const float* __restrict__ W2, const float* __restrict__ b2,
                       float* __restrict__ out) {
    int warp = (blockIdx.x * blockDim.x + threadIdx.x) >> 5;
    int lane = threadIdx.x & 31;
    if (warp >= NB) return;
    const float2* row2 = (const float2*)&g_o1[(size_t)warp * HID];
    const float4* w4   = (const float4*)W2;
    float s0 = 0.f, s1 = 0.f;
#pragma unroll 5
    for (int j2 = lane; j2 < HID / 2; j2 += 32) {
        float2 v = row2[j2];
        float4 w = w4[j2];
        s0 = fmaf(v.x, w.x, fmaf(v.y, w.z, s0));
        s1 = fmaf(v.x, w.y, fmaf(v.y, w.w, s1));
    }
#pragma unroll
    for (int off = 16; off > 0; off >>= 1) {
        s0 += __shfl_down_sync(0xffffffffu, s0, off);
        s1 += __shfl_down_sync(0xffffffffu, s1, off);
    }
    if (lane == 0) {
        float l0 = s0 + b2[0];
        float l1 = s1 + b2[1];
        float m  = fmaxf(l0, l1);
        float e0 = expf(l0 - m);
        float e1 = expf(l1 - m);
        float inv = 1.f / (e0 + e1);
        out[warp * 2 + 0] = e0 * inv;
        out[warp * 2 + 1] = e1 * inv;
    }
}

// ---------------- launch ----------------
extern "C" void kernel_launch(void* const* d_in, const int* in_sizes, int n_in,
                              void* d_out, int out_size) {
    const float* x  = (const float*)d_in[0];
    const int*   ei = (const int*)  d_in[1];
    const float* Wc = (const float*)d_in[3];
    const float* bc = (const float*)d_in[4];
    const float* W1 = (const float*)d_in[5];
    const float* b1 = (const float*)d_in[6];
    const float* W2 = (const float*)d_in[7];
    const float* b2 = (const float*)d_in[8];
    float* out = (float*)d_out;

    float *po1, *pdinv;
    __half* phs;
    __nv_bfloat16 *ph2b, *pW1b;
    cudaGetSymbolAddress((void**)&phs,  g_hs);
    cudaGetSymbolAddress((void**)&po1,  g_o1);
    cudaGetSymbolAddress((void**)&pdinv, g_dinv);
    cudaGetSymbolAddress((void**)&ph2b, g_h2b);
    cudaGetSymbolAddress((void**)&pW1b, g_W1b);

    static int smem_set = 0;
    if (!smem_set) {
        cudaFuncSetAttribute(k_gemm_conv<DD, DD, DD / BK>,
                             cudaFuncAttributeMaxDynamicSharedMemorySize, SM_TOTAL_B);
        smem_set = 1;
    }

    const int* src = ei;        // edge_index[0]
    const int* dst = ei + EE;   // edge_index[1]

    // degrees + CSR offsets + fill
    k_deg_init <<<(NN + 255) / 256, 256>>>();
    k_deg_count<<<(EE / 4 + 255) / 256, 256>>>(dst);
    k_dinv     <<<(NN + 255) / 256, 256>>>();
    k_scan1    <<<NBLK, 1024>>>();
    k_scan2    <<<1, 32>>>();
    k_scan3    <<<NBLK, 1024>>>();
    k_fill     <<<(EE / 4 + 255) / 256, 256>>>(src, dst);

    // W1 -> bf16
    k_cvt_w1<<<((size_t)HID * HID / 4 + 255) / 256, 256>>>(W1);

    // hs = fp16((x @ W_conv) * dinv[row])
    {
        dim3 grid(DD / BN, NN / BM);
        k_gemm_conv<DD, DD, DD / BK>
            <<<grid, 256, SM_TOTAL_B>>>(x, Wc, phs, pdinv);
    }

    // CSR gather aggregate + bias + relu + bf16 cvt
    k_aggregate<<<NN / 8, 256>>>(bc);

    // o1 = relu(H @ W1 + b1) — bf16 mma
    {
        dim3 grid(HID / BN, NB / BM);
        k_gemm_bf16<<<grid, 256>>>(ph2b, pW1b, po1, b1);
    }

    // logits + softmax
    k_head<<<(NB * 32 + 255) / 256, 256>>>(W2, b2, out);
}